// round 3
// baseline (speedup 1.0000x reference)
#include <cuda_runtime.h>
#include <math.h>

// Problem constants
#define L_    2048
#define NB    2
#define E_    2048
#define I_    2048
#define H_    16
#define DH    128
#define ROWS  (L_*NB)   // 4096 rows for all GEMMs

// Scratch (device globals — no allocations allowed)
__device__ float g_Q[(size_t)ROWS * I_];
__device__ float g_K[(size_t)ROWS * I_];
__device__ float g_V[(size_t)ROWS * I_];
__device__ float g_C[(size_t)ROWS * I_];

// ---------------------------------------------------------------------------
// GEMM:  C[M,Nn] = alpha * (A[M,K] @ B[Nn,K]^T + bias[Nn])
// A, B row-major with K innermost (NT gemm). M,Nn multiples of 128, K of 8.
// 256 threads, 128x128 tile, BK=8, 8x8 per-thread microtile (strided halves).
// Aopt == nullptr -> A = g_C. Copt == nullptr -> C selected by out_tag.
// ---------------------------------------------------------------------------
__global__ __launch_bounds__(256) void gemm_nt_bias(
    const float* __restrict__ Aopt, const float* __restrict__ B,
    const float* __restrict__ bias, float* __restrict__ Copt, int out_tag,
    int M, int Nn, int K, float alpha)
{
    const float* A = Aopt ? Aopt : g_C;
    float* C = Copt ? Copt : (out_tag == 0 ? g_Q : (out_tag == 1 ? g_K : g_V));

    __shared__ float As[8][128];
    __shared__ float Bs[8][128];

    const int tid = threadIdx.x;
    const int bm = blockIdx.y * 128;
    const int bn = blockIdx.x * 128;
    const int tx = tid & 15;
    const int ty = tid >> 4;
    const int lr = tid >> 1;           // 0..127 (tile row for loads)
    const int lc = (tid & 1) * 4;      // 0 or 4 (k-offset for loads)

    const float* Ap = A + (size_t)(bm + lr) * K + lc;
    const float* Bp = B + (size_t)(bn + lr) * K + lc;

    float acc[8][8];
#pragma unroll
    for (int i = 0; i < 8; i++)
#pragma unroll
        for (int j = 0; j < 8; j++) acc[i][j] = 0.0f;

    for (int k0 = 0; k0 < K; k0 += 8) {
        float4 av = *(const float4*)(Ap + k0);
        float4 bv = *(const float4*)(Bp + k0);
        __syncthreads();
        As[lc + 0][lr] = av.x; As[lc + 1][lr] = av.y;
        As[lc + 2][lr] = av.z; As[lc + 3][lr] = av.w;
        Bs[lc + 0][lr] = bv.x; Bs[lc + 1][lr] = bv.y;
        Bs[lc + 2][lr] = bv.z; Bs[lc + 3][lr] = bv.w;
        __syncthreads();
#pragma unroll
        for (int kk = 0; kk < 8; kk++) {
            float4 a0 = *(const float4*)&As[kk][4 * ty];
            float4 a1 = *(const float4*)&As[kk][64 + 4 * ty];
            float4 b0 = *(const float4*)&Bs[kk][4 * tx];
            float4 b1 = *(const float4*)&Bs[kk][64 + 4 * tx];
            float ar[8] = {a0.x, a0.y, a0.z, a0.w, a1.x, a1.y, a1.z, a1.w};
            float br[8] = {b0.x, b0.y, b0.z, b0.w, b1.x, b1.y, b1.z, b1.w};
#pragma unroll
            for (int i = 0; i < 8; i++)
#pragma unroll
                for (int j = 0; j < 8; j++)
                    acc[i][j] += ar[i] * br[j];
        }
    }

    float4 bb0 = *(const float4*)&bias[bn + 4 * tx];
    float4 bb1 = *(const float4*)&bias[bn + 64 + 4 * tx];
    float bcol[8] = {bb0.x, bb0.y, bb0.z, bb0.w, bb1.x, bb1.y, bb1.z, bb1.w};
#pragma unroll
    for (int i = 0; i < 8; i++) {
        int r = bm + ((i < 4) ? (4 * ty + i) : (64 + 4 * ty + (i - 4)));
        float4 o0, o1;
        o0.x = alpha * (acc[i][0] + bcol[0]);
        o0.y = alpha * (acc[i][1] + bcol[1]);
        o0.z = alpha * (acc[i][2] + bcol[2]);
        o0.w = alpha * (acc[i][3] + bcol[3]);
        o1.x = alpha * (acc[i][4] + bcol[4]);
        o1.y = alpha * (acc[i][5] + bcol[5]);
        o1.z = alpha * (acc[i][6] + bcol[6]);
        o1.w = alpha * (acc[i][7] + bcol[7]);
        *(float4*)&C[(size_t)r * Nn + bn + 4 * tx] = o0;
        *(float4*)&C[(size_t)r * Nn + bn + 64 + 4 * tx] = o1;
    }
}

// ---------------------------------------------------------------------------
// Causal flash attention, fp32, 48KB dynamic smem (no opt-in attribute).
// Q/K/V layout: [ROWS, I_] where row = l*NB + n, col = h*DH + d.
// Grid: (qtile=32, batch=32 (n,h)), 256 threads. Bq=64, Bk=32.
// Smem: Qt[128][64] (32KB) | work 16KB: Kt[128][32] -> P[64][32] + Vc[32][64].
// ---------------------------------------------------------------------------
__global__ __launch_bounds__(256) void flash_attn()
{
    extern __shared__ float sm[];
    float* Qt = sm;             // 8192 floats (k-major Q tile)
    float* Wk = sm + 8192;      // 4096 floats work region
    float* Ps = Wk;             // P[64][32] (2048 floats)
    float* Vc = Wk + 2048;      // V chunk [32][64] (2048 floats)

    const int tid = threadIdx.x;
    const int tx = tid & 15;     // column group
    const int ty = tid >> 4;     // row group
    const int qt = blockIdx.x;
    const int b  = blockIdx.y;
    const int n  = b / H_;
    const int h  = b % H_;
    const int q0 = qt * 64;
    const int colbase = h * DH;

    // Load Q tile transposed: Qt[k][r], r in 0..63
    for (int idx = tid; idx < 64 * 32; idx += 256) {
        int r  = idx >> 5;
        int c4 = idx & 31;
        const float4 v = *(const float4*)&g_Q[(size_t)((q0 + r) * NB + n) * I_ + colbase + 4 * c4];
        Qt[(4 * c4 + 0) * 64 + r] = v.x;
        Qt[(4 * c4 + 1) * 64 + r] = v.y;
        Qt[(4 * c4 + 2) * 64 + r] = v.z;
        Qt[(4 * c4 + 3) * 64 + r] = v.w;
    }

    float o[4][8];
#pragma unroll
    for (int i = 0; i < 4; i++)
#pragma unroll
        for (int c = 0; c < 8; c++) o[i][c] = 0.0f;
    float m_run[4], l_run[4];
#pragma unroll
    for (int i = 0; i < 4; i++) { m_run[i] = -1e30f; l_run[i] = 0.0f; }

    const int jt_max = 2 * qt + 1;   // kv tiles of 32 rows
    for (int jt = 0; jt <= jt_max; jt++) {
        const int k0 = jt * 32;

        __syncthreads();  // prior iteration's work-region readers done
        // Load K tile transposed: Kt[k][r], r in 0..31 (Kt aliases Wk)
        for (int idx = tid; idx < 32 * 32; idx += 256) {
            int r  = idx >> 5;
            int c4 = idx & 31;
            const float4 kv = *(const float4*)&g_K[(size_t)((k0 + r) * NB + n) * I_ + colbase + 4 * c4];
            Wk[(4 * c4 + 0) * 32 + r] = kv.x;
            Wk[(4 * c4 + 1) * 32 + r] = kv.y;
            Wk[(4 * c4 + 2) * 32 + r] = kv.z;
            Wk[(4 * c4 + 3) * 32 + r] = kv.w;
        }
        __syncthreads();

        // S = Q @ K^T  (4x2 per thread: rows 4ty+i, cols 2tx+j)
        float s[4][2];
#pragma unroll
        for (int i = 0; i < 4; i++) { s[i][0] = 0.0f; s[i][1] = 0.0f; }

        const float4* Qt4 = (const float4*)Qt;
        const float2* Kt2 = (const float2*)Wk;
#pragma unroll 4
        for (int k = 0; k < 128; k++) {
            float4 qa = Qt4[k * 16 + ty];
            float2 kb = Kt2[k * 16 + tx];
            float qr[4] = {qa.x, qa.y, qa.z, qa.w};
#pragma unroll
            for (int i = 0; i < 4; i++) {
                s[i][0] += qr[i] * kb.x;
                s[i][1] += qr[i] * kb.y;
            }
        }

        // Causal mask (only the last two kv tiles straddle the diagonal)
        if (jt >= 2 * qt) {
#pragma unroll
            for (int i = 0; i < 4; i++)
#pragma unroll
                for (int j = 0; j < 2; j++)
                    if (k0 + 2 * tx + j > q0 + 4 * ty + i) s[i][j] = -1e30f;
        }

        // Online softmax (row = 16 aligned lanes: same ty within warp)
#pragma unroll
        for (int i = 0; i < 4; i++) {
            float mt = fmaxf(s[i][0], s[i][1]);
#pragma unroll
            for (int off = 1; off < 16; off <<= 1)
                mt = fmaxf(mt, __shfl_xor_sync(0xffffffffu, mt, off));
            float mnew = fmaxf(m_run[i], mt);
            float corr = __expf(m_run[i] - mnew);
            m_run[i] = mnew;
            s[i][0] = __expf(s[i][0] - mnew);
            s[i][1] = __expf(s[i][1] - mnew);
            float rs = s[i][0] + s[i][1];
#pragma unroll
            for (int off = 1; off < 16; off <<= 1)
                rs += __shfl_xor_sync(0xffffffffu, rs, off);
            l_run[i] = l_run[i] * corr + rs;
#pragma unroll
            for (int c = 0; c < 8; c++) o[i][c] *= corr;
        }

        __syncthreads();  // all Kt reads done; work region reusable

        // Write P (overwrites Kt low half) and load V chunk 0 (high half)
        float2* Ps2 = (float2*)Ps;
#pragma unroll
        for (int i = 0; i < 4; i++)
            Ps2[(4 * ty + i) * 16 + tx] = make_float2(s[i][0], s[i][1]);
        for (int idx = tid; idx < 32 * 16; idx += 256) {
            int r  = idx >> 4;
            int c4 = idx & 15;
            ((float4*)Vc)[r * 16 + c4] =
                *(const float4*)&g_V[(size_t)((k0 + r) * NB + n) * I_ + colbase + 4 * c4];
        }
        __syncthreads();

        // O[:, 0:64] += P @ V[:, 0:64]
        const float4* Vc4 = (const float4*)Vc;
#pragma unroll 2
        for (int kk = 0; kk < 32; kk++) {
            float4 v0 = Vc4[kk * 16 + tx];
#pragma unroll
            for (int i = 0; i < 4; i++) {
                float p = Ps[(4 * ty + i) * 32 + kk];
                o[i][0] += p * v0.x; o[i][1] += p * v0.y;
                o[i][2] += p * v0.z; o[i][3] += p * v0.w;
            }
        }
        __syncthreads();

        // Load V chunk 1
        for (int idx = tid; idx < 32 * 16; idx += 256) {
            int r  = idx >> 4;
            int c4 = idx & 15;
            ((float4*)Vc)[r * 16 + c4] =
                *(const float4*)&g_V[(size_t)((k0 + r) * NB + n) * I_ + colbase + 64 + 4 * c4];
        }
        __syncthreads();

        // O[:, 64:128] += P @ V[:, 64:128]
#pragma unroll 2
        for (int kk = 0; kk < 32; kk++) {
            float4 v1 = Vc4[kk * 16 + tx];
#pragma unroll
            for (int i = 0; i < 4; i++) {
                float p = Ps[(4 * ty + i) * 32 + kk];
                o[i][4] += p * v1.x; o[i][5] += p * v1.y;
                o[i][6] += p * v1.z; o[i][7] += p * v1.w;
            }
        }
    }

    // Normalize and store (cols 4tx..4tx+3 and 64+4tx..64+4tx+3)
#pragma unroll
    for (int i = 0; i < 4; i++) {
        float inv = 1.0f / l_run[i];
        size_t base = (size_t)((q0 + 4 * ty + i) * NB + n) * I_ + colbase;
        float4 r0 = {o[i][0] * inv, o[i][1] * inv, o[i][2] * inv, o[i][3] * inv};
        float4 r1 = {o[i][4] * inv, o[i][5] * inv, o[i][6] * inv, o[i][7] * inv};
        *(float4*)&g_C[base + 4 * tx] = r0;
        *(float4*)&g_C[base + 64 + 4 * tx] = r1;
    }
}

// ---------------------------------------------------------------------------
// kernel_launch: pure kernel launches, no runtime API calls of any kind.
// ---------------------------------------------------------------------------
extern "C" void kernel_launch(void* const* d_in, const int* in_sizes, int n_in,
                              void* d_out, int out_size)
{
    (void)in_sizes; (void)n_in; (void)out_size;
    const float* query = (const float*)d_in[0];
    const float* qw    = (const float*)d_in[1];
    const float* qb    = (const float*)d_in[2];
    const float* kw    = (const float*)d_in[3];
    const float* kb    = (const float*)d_in[4];
    const float* vw    = (const float*)d_in[5];
    const float* vb    = (const float*)d_in[6];
    const float* ow    = (const float*)d_in[7];
    const float* ob    = (const float*)d_in[8];
    float* out = (float*)d_out;

    const float scale = 0.08838834764831845f;  // 1/sqrt(128)
    dim3 gg(I_ / 128, ROWS / 128);             // (16, 32)

    gemm_nt_bias<<<gg, 256>>>(query, qw, qb, nullptr, 0, ROWS, I_, E_, scale);
    gemm_nt_bias<<<gg, 256>>>(query, kw, kb, nullptr, 1, ROWS, I_, E_, 1.0f);
    gemm_nt_bias<<<gg, 256>>>(query, vw, vb, nullptr, 2, ROWS, I_, E_, 1.0f);
    flash_attn<<<dim3(L_ / 64, NB * H_), 256, 48 * 1024>>>();
    gemm_nt_bias<<<gg, 256>>>(nullptr, ow, ob, out, 3, ROWS, E_, I_, 1.0f);
}

// round 6
// speedup vs baseline: 1.4269x; 1.4269x over previous
// v5r: identical to round-5 submission (broker infra failure; re-audited OK).
#include <cuda_runtime.h>
#include <cuda_bf16.h>
#include <stdint.h>
#include <math.h>

// Problem constants
#define L_    2048
#define NB    2
#define E_    2048
#define I_    2048
#define H_    16
#define DH    128
#define ROWS  (L_*NB)        // 4096
#define WELEM (I_*E_)        // 4194304

// ---------------------------------------------------------------------------
// Scratch (device globals — no allocations allowed)
// ---------------------------------------------------------------------------
__device__ float g_Q[(size_t)ROWS * I_];
__device__ float g_K[(size_t)ROWS * I_];
__device__ float g_V[(size_t)ROWS * I_];
__device__ float g_C[(size_t)ROWS * I_];
__device__ __nv_bfloat16 g_Ahi[(size_t)ROWS * I_];
__device__ __nv_bfloat16 g_Alo[(size_t)ROWS * I_];
__device__ __nv_bfloat16 g_Whi[(size_t)4 * WELEM];
__device__ __nv_bfloat16 g_Wlo[(size_t)4 * WELEM];

// ---------------------------------------------------------------------------
// Small PTX helpers (all plain sm_80-era ISA; no sm_103a features)
// ---------------------------------------------------------------------------
static __device__ __forceinline__ uint32_t smem_u32(const void* p) {
    uint32_t a;
    asm("{ .reg .u64 t; cvta.to.shared.u64 t, %1; cvt.u32.u64 %0, t; }"
        : "=r"(a) : "l"(p));
    return a;
}
static __device__ __forceinline__ void cp_async16(uint32_t dst, const void* src) {
    asm volatile("cp.async.cg.shared.global [%0], [%1], 16;" :: "r"(dst), "l"(src));
}
static __device__ __forceinline__ void cp_commit() {
    asm volatile("cp.async.commit_group;");
}
static __device__ __forceinline__ void cp_wait1() {
    asm volatile("cp.async.wait_group 1;" ::: "memory");
}
static __device__ __forceinline__ void cp_wait0() {
    asm volatile("cp.async.wait_group 0;" ::: "memory");
}
static __device__ __forceinline__ void ldm_x4(uint32_t& r0, uint32_t& r1,
                                              uint32_t& r2, uint32_t& r3, uint32_t a) {
    asm volatile("ldmatrix.sync.aligned.m8n8.x4.shared.b16 {%0,%1,%2,%3}, [%4];"
                 : "=r"(r0), "=r"(r1), "=r"(r2), "=r"(r3) : "r"(a));
}
static __device__ __forceinline__ void mma_bf16(float* d, const uint32_t* a,
                                                const uint32_t* b) {
    asm volatile(
        "mma.sync.aligned.m16n8k16.row.col.f32.bf16.bf16.f32 "
        "{%0,%1,%2,%3}, {%4,%5,%6,%7}, {%8,%9}, {%0,%1,%2,%3};"
        : "+f"(d[0]), "+f"(d[1]), "+f"(d[2]), "+f"(d[3])
        : "r"(a[0]), "r"(a[1]), "r"(a[2]), "r"(a[3]), "r"(b[0]), "r"(b[1]));
}

// ---------------------------------------------------------------------------
// fp32 -> (hi, lo) bf16 split. dst_tag: 0 -> g_Ahi/g_Alo, 1..4 -> weight w-1.
// src==nullptr -> read g_C.
// ---------------------------------------------------------------------------
__global__ __launch_bounds__(256) void split_fp32(
    const float* __restrict__ srcOpt, int dst_tag, int n)
{
    const float* src = srcOpt ? srcOpt : g_C;
    __nv_bfloat16 *hi, *lo;
    if (dst_tag == 0) { hi = g_Ahi; lo = g_Alo; }
    else {
        hi = g_Whi + (size_t)(dst_tag - 1) * WELEM;
        lo = g_Wlo + (size_t)(dst_tag - 1) * WELEM;
    }
    int i = blockIdx.x * blockDim.x + threadIdx.x;
    int stride = gridDim.x * blockDim.x;
    for (; 4 * i < n; i += stride) {
        float4 v = ((const float4*)src)[i];
        __nv_bfloat16 hx = __float2bfloat16(v.x);
        __nv_bfloat16 hy = __float2bfloat16(v.y);
        __nv_bfloat16 hz = __float2bfloat16(v.z);
        __nv_bfloat16 hw = __float2bfloat16(v.w);
        __nv_bfloat16 lx = __float2bfloat16(v.x - __bfloat162float(hx));
        __nv_bfloat16 ly = __float2bfloat16(v.y - __bfloat162float(hy));
        __nv_bfloat16 lz = __float2bfloat16(v.z - __bfloat162float(hz));
        __nv_bfloat16 lw = __float2bfloat16(v.w - __bfloat162float(hw));
        __nv_bfloat162* h2 = (__nv_bfloat162*)(hi + (size_t)4 * i);
        __nv_bfloat162* l2 = (__nv_bfloat162*)(lo + (size_t)4 * i);
        h2[0] = __halves2bfloat162(hx, hy);
        h2[1] = __halves2bfloat162(hz, hw);
        l2[0] = __halves2bfloat162(lx, ly);
        l2[1] = __halves2bfloat162(lz, lw);
    }
}

// ---------------------------------------------------------------------------
// Split-bf16 GEMM on mma.sync (HMMA): C[4096,2048] =
//   alpha * ((Ah+Al) @ (Bh+Bl)^T + bias),  dropping Al*Bl.
// Tile 128x128, BK=16, double-buffered cp.async. 8 warps as 2(m) x 4(n),
// warp tile 64x32: 4 m-frags x 4 n-frags x 3 products = 48 HMMA/warp/stage.
// SMEM: 4 tiles of [128 rows x 24 halves] (48B stride -> conflict-free
// ldmatrix) x 2 stages = 49152 B exactly (no attribute needed).
// ---------------------------------------------------------------------------
#define BSTR   24            // halves per smem row (16 data + 8 pad)
#define TILE_B (128*BSTR*2)  // 6144 bytes per tile
#define STG_B  (4*TILE_B)    // 24576 bytes per stage

__global__ __launch_bounds__(256) void gemm_mma(
    int w_idx, const float* __restrict__ bias,
    float* __restrict__ Copt, int out_tag, float alpha)
{
    extern __shared__ __align__(16) char smem[];
    const uint32_t sbase = smem_u32(smem);

    const int tid  = threadIdx.x;
    const int wid  = tid >> 5;
    const int lane = tid & 31;
    const int wm = wid >> 2;          // 0..1
    const int wn = wid & 3;           // 0..3
    const int bm = blockIdx.y * 128;
    const int bn = blockIdx.x * 128;

    const __nv_bfloat16* Ahi = g_Ahi;
    const __nv_bfloat16* Alo = g_Alo;
    const __nv_bfloat16* Bhi = g_Whi + (size_t)w_idx * WELEM;
    const __nv_bfloat16* Blo = g_Wlo + (size_t)w_idx * WELEM;
    float* C = Copt ? Copt : (out_tag == 0 ? g_Q : (out_tag == 1 ? g_K : g_V));

    // Loader mapping: 1024 x 16B chunks per stage; 4 per thread.
    // idx: tile(2b) | row(7b) | half(1b)
    int lrow[4], lhalf[4], ltile[4]; uint32_t ldst[4];
#pragma unroll
    for (int t = 0; t < 4; t++) {
        int idx = tid + t * 256;
        ltile[t] = idx >> 8;
        lrow[t]  = (idx >> 1) & 127;
        lhalf[t] = idx & 1;
        ldst[t]  = (uint32_t)(ltile[t] * TILE_B + lrow[t] * (BSTR * 2) + lhalf[t] * 16);
    }
    const __nv_bfloat16* lsrc[4];
#pragma unroll
    for (int t = 0; t < 4; t++) {
        const __nv_bfloat16* base =
            (ltile[t] == 0) ? Ahi : (ltile[t] == 1) ? Alo : (ltile[t] == 2) ? Bhi : Blo;
        int row = (ltile[t] < 2 ? bm : bn) + lrow[t];
        lsrc[t] = base + (size_t)row * 2048 + lhalf[t] * 8;
    }

    // Fragment smem offsets (lane-dependent)
    const int frow = lane & 15;
    const int fhal = lane >> 4;
    const uint32_t a_base = (uint32_t)((wm * 64 + frow) * (BSTR * 2) + fhal * 16);
    const uint32_t b_base = (uint32_t)((wn * 32 + frow) * (BSTR * 2) + fhal * 16);

    float acc[4][4][4];
#pragma unroll
    for (int i = 0; i < 4; i++)
#pragma unroll
        for (int j = 0; j < 4; j++)
#pragma unroll
            for (int q = 0; q < 4; q++) acc[i][j][q] = 0.0f;

    // Prologue: stage 0
#pragma unroll
    for (int t = 0; t < 4; t++)
        cp_async16(sbase + ldst[t], lsrc[t]);
    cp_commit();

    for (int s = 0; s < 128; s++) {
        if (s + 1 < 128) {
            const uint32_t stg = (uint32_t)(((s + 1) & 1) * STG_B);
#pragma unroll
            for (int t = 0; t < 4; t++)
                cp_async16(sbase + stg + ldst[t], lsrc[t] + (s + 1) * 16);
            cp_commit();
            cp_wait1();
        } else {
            cp_wait0();
        }
        __syncthreads();

        const uint32_t stg = sbase + (uint32_t)((s & 1) * STG_B);

        // B fragments: hi and lo, 4 n8-frags each via 2 ldmatrix.x4
        uint32_t bh[4][2], bl[4][2];
#pragma unroll
        for (int pair = 0; pair < 2; pair++) {
            uint32_t r0, r1, r2, r3;
            ldm_x4(r0, r1, r2, r3, stg + 2 * TILE_B + b_base + (uint32_t)(pair * 16 * BSTR * 2));
            bh[2 * pair][0] = r0; bh[2 * pair][1] = r2;
            bh[2 * pair + 1][0] = r1; bh[2 * pair + 1][1] = r3;
            ldm_x4(r0, r1, r2, r3, stg + 3 * TILE_B + b_base + (uint32_t)(pair * 16 * BSTR * 2));
            bl[2 * pair][0] = r0; bl[2 * pair][1] = r2;
            bl[2 * pair + 1][0] = r1; bl[2 * pair + 1][1] = r3;
        }

#pragma unroll
        for (int mf = 0; mf < 4; mf++) {
            uint32_t ah[4], al[4];
            ldm_x4(ah[0], ah[1], ah[2], ah[3],
                   stg + a_base + (uint32_t)(mf * 16 * BSTR * 2));
            ldm_x4(al[0], al[1], al[2], al[3],
                   stg + TILE_B + a_base + (uint32_t)(mf * 16 * BSTR * 2));
#pragma unroll
            for (int nf = 0; nf < 4; nf++) {
                mma_bf16(acc[mf][nf], ah, bh[nf]);
                mma_bf16(acc[mf][nf], ah, bl[nf]);
                mma_bf16(acc[mf][nf], al, bh[nf]);
            }
        }
        __syncthreads();
    }

    // Epilogue: alpha * (acc + bias)
#pragma unroll
    for (int mf = 0; mf < 4; mf++) {
#pragma unroll
        for (int nf = 0; nf < 4; nf++) {
            const int row0 = bm + wm * 64 + mf * 16 + (lane >> 2);
            const int col  = bn + wn * 32 + nf * 8 + (lane & 3) * 2;
            float2 bv = *(const float2*)&bias[col];
            float2 o0, o1;
            o0.x = alpha * (acc[mf][nf][0] + bv.x);
            o0.y = alpha * (acc[mf][nf][1] + bv.y);
            o1.x = alpha * (acc[mf][nf][2] + bv.x);
            o1.y = alpha * (acc[mf][nf][3] + bv.y);
            *(float2*)&C[(size_t)row0 * 2048 + col] = o0;
            *(float2*)&C[(size_t)(row0 + 8) * 2048 + col] = o1;
        }
    }
}

// ---------------------------------------------------------------------------
// Causal flash attention, fp32, 48KB dynamic smem (unchanged, passing).
// ---------------------------------------------------------------------------
__global__ __launch_bounds__(256) void flash_attn()
{
    extern __shared__ float sm[];
    float* Qt = sm;             // 8192 floats (k-major Q tile)
    float* Wk = sm + 8192;      // 4096 floats work region
    float* Ps = Wk;             // P[64][32]
    float* Vc = Wk + 2048;      // V chunk [32][64]

    const int tid = threadIdx.x;
    const int tx = tid & 15;
    const int ty = tid >> 4;
    const int qt = blockIdx.x;
    const int b  = blockIdx.y;
    const int n  = b / H_;
    const int h  = b % H_;
    const int q0 = qt * 64;
    const int colbase = h * DH;

    for (int idx = tid; idx < 64 * 32; idx += 256) {
        int r  = idx >> 5;
        int c4 = idx & 31;
        const float4 v = *(const float4*)&g_Q[(size_t)((q0 + r) * NB + n) * I_ + colbase + 4 * c4];
        Qt[(4 * c4 + 0) * 64 + r] = v.x;
        Qt[(4 * c4 + 1) * 64 + r] = v.y;
        Qt[(4 * c4 + 2) * 64 + r] = v.z;
        Qt[(4 * c4 + 3) * 64 + r] = v.w;
    }

    float o[4][8];
#pragma unroll
    for (int i = 0; i < 4; i++)
#pragma unroll
        for (int c = 0; c < 8; c++) o[i][c] = 0.0f;
    float m_run[4], l_run[4];
#pragma unroll
    for (int i = 0; i < 4; i++) { m_run[i] = -1e30f; l_run[i] = 0.0f; }

    const int jt_max = 2 * qt + 1;
    for (int jt = 0; jt <= jt_max; jt++) {
        const int k0 = jt * 32;

        __syncthreads();
        for (int idx = tid; idx < 32 * 32; idx += 256) {
            int r  = idx >> 5;
            int c4 = idx & 31;
            const float4 kv = *(const float4*)&g_K[(size_t)((k0 + r) * NB + n) * I_ + colbase + 4 * c4];
            Wk[(4 * c4 + 0) * 32 + r] = kv.x;
            Wk[(4 * c4 + 1) * 32 + r] = kv.y;
            Wk[(4 * c4 + 2) * 32 + r] = kv.z;
            Wk[(4 * c4 + 3) * 32 + r] = kv.w;
        }
        __syncthreads();

        float s[4][2];
#pragma unroll
        for (int i = 0; i < 4; i++) { s[i][0] = 0.0f; s[i][1] = 0.0f; }

        const float4* Qt4 = (const float4*)Qt;
        const float2* Kt2 = (const float2*)Wk;
#pragma unroll 4
        for (int k = 0; k < 128; k++) {
            float4 qa = Qt4[k * 16 + ty];
            float2 kb = Kt2[k * 16 + tx];
            float qr[4] = {qa.x, qa.y, qa.z, qa.w};
#pragma unroll
            for (int i = 0; i < 4; i++) {
                s[i][0] += qr[i] * kb.x;
                s[i][1] += qr[i] * kb.y;
            }
        }

        if (jt >= 2 * qt) {
#pragma unroll
            for (int i = 0; i < 4; i++)
#pragma unroll
                for (int j = 0; j < 2; j++)
                    if (k0 + 2 * tx + j > q0 + 4 * ty + i) s[i][j] = -1e30f;
        }

#pragma unroll
        for (int i = 0; i < 4; i++) {
            float mt = fmaxf(s[i][0], s[i][1]);
#pragma unroll
            for (int off = 1; off < 16; off <<= 1)
                mt = fmaxf(mt, __shfl_xor_sync(0xffffffffu, mt, off));
            float mnew = fmaxf(m_run[i], mt);
            float corr = __expf(m_run[i] - mnew);
            m_run[i] = mnew;
            s[i][0] = __expf(s[i][0] - mnew);
            s[i][1] = __expf(s[i][1] - mnew);
            float rs = s[i][0] + s[i][1];
#pragma unroll
            for (int off = 1; off < 16; off <<= 1)
                rs += __shfl_xor_sync(0xffffffffu, rs, off);
            l_run[i] = l_run[i] * corr + rs;
#pragma unroll
            for (int c = 0; c < 8; c++) o[i][c] *= corr;
        }

        __syncthreads();

        float2* Ps2 = (float2*)Ps;
#pragma unroll
        for (int i = 0; i < 4; i++)
            Ps2[(4 * ty + i) * 16 + tx] = make_float2(s[i][0], s[i][1]);
        for (int idx = tid; idx < 32 * 16; idx += 256) {
            int r  = idx >> 4;
            int c4 = idx & 15;
            ((float4*)Vc)[r * 16 + c4] =
                *(const float4*)&g_V[(size_t)((k0 + r) * NB + n) * I_ + colbase + 4 * c4];
        }
        __syncthreads();

        const float4* Vc4 = (const float4*)Vc;
#pragma unroll 2
        for (int kk = 0; kk < 32; kk++) {
            float4 v0 = Vc4[kk * 16 + tx];
#pragma unroll
            for (int i = 0; i < 4; i++) {
                float p = Ps[(4 * ty + i) * 32 + kk];
                o[i][0] += p * v0.x; o[i][1] += p * v0.y;
                o[i][2] += p * v0.z; o[i][3] += p * v0.w;
            }
        }
        __syncthreads();

        for (int idx = tid; idx < 32 * 16; idx += 256) {
            int r  = idx >> 4;
            int c4 = idx & 15;
            ((float4*)Vc)[r * 16 + c4] =
                *(const float4*)&g_V[(size_t)((k0 + r) * NB + n) * I_ + colbase + 64 + 4 * c4];
        }
        __syncthreads();

#pragma unroll 2
        for (int kk = 0; kk < 32; kk++) {
            float4 v1 = Vc4[kk * 16 + tx];
#pragma unroll
            for (int i = 0; i < 4; i++) {
                float p = Ps[(4 * ty + i) * 32 + kk];
                o[i][4] += p * v1.x; o[i][5] += p * v1.y;
                o[i][6] += p * v1.z; o[i][7] += p * v1.w;
            }
        }
    }

#pragma unroll
    for (int i = 0; i < 4; i++) {
        float inv = 1.0f / l_run[i];
        size_t base = (size_t)((q0 + 4 * ty + i) * NB + n) * I_ + colbase;
        float4 r0 = {o[i][0] * inv, o[i][1] * inv, o[i][2] * inv, o[i][3] * inv};
        float4 r1 = {o[i][4] * inv, o[i][5] * inv, o[i][6] * inv, o[i][7] * inv};
        *(float4*)&g_C[base + 4 * tx] = r0;
        *(float4*)&g_C[base + 64 + 4 * tx] = r1;
    }
}

// ---------------------------------------------------------------------------
// kernel_launch: pure kernel launches only.
// ---------------------------------------------------------------------------
extern "C" void kernel_launch(void* const* d_in, const int* in_sizes, int n_in,
                              void* d_out, int out_size)
{
    (void)in_sizes; (void)n_in; (void)out_size;
    const float* query = (const float*)d_in[0];
    const float* qw    = (const float*)d_in[1];
    const float* qb    = (const float*)d_in[2];
    const float* kw    = (const float*)d_in[3];
    const float* kb    = (const float*)d_in[4];
    const float* vw    = (const float*)d_in[5];
    const float* vb    = (const float*)d_in[6];
    const float* ow    = (const float*)d_in[7];
    const float* ob    = (const float*)d_in[8];
    float* out = (float*)d_out;

    const float scale = 0.08838834764831845f;  // 1/sqrt(128)
    const int nA = ROWS * I_;   // 8388608
    const int nW = WELEM;       // 4194304
    dim3 gg(16, 32);            // (N/128, M/128)

    // Split inputs to (hi, lo) bf16
    split_fp32<<<nA / 1024, 256>>>(query, 0, nA);
    split_fp32<<<nW / 1024, 256>>>(qw, 1, nW);
    split_fp32<<<nW / 1024, 256>>>(kw, 2, nW);
    split_fp32<<<nW / 1024, 256>>>(vw, 3, nW);
    split_fp32<<<nW / 1024, 256>>>(ow, 4, nW);

    // Projections (HMMA tensor cores, split-bf16)
    gemm_mma<<<gg, 256, 2 * STG_B>>>(0, qb, nullptr, 0, scale);
    gemm_mma<<<gg, 256, 2 * STG_B>>>(1, kb, nullptr, 1, 1.0f);
    gemm_mma<<<gg, 256, 2 * STG_B>>>(2, vb, nullptr, 2, 1.0f);

    // Attention
    flash_attn<<<dim3(L_ / 64, NB * H_), 256, 48 * 1024>>>();

    // Output projection
    split_fp32<<<nA / 1024, 256>>>(nullptr, 0, nA);  // g_C -> Ahi/Alo
    gemm_mma<<<gg, 256, 2 * STG_B>>>(3, ob, out, 3, 1.0f);
}

// round 8
// speedup vs baseline: 2.4750x; 1.7346x over previous
// v7: HMMA flash attention (split-bf16) + fused split epilogues in GEMM.
#include <cuda_runtime.h>
#include <cuda_bf16.h>
#include <stdint.h>
#include <math.h>

#define L_    2048
#define NB    2
#define E_    2048
#define I_    2048
#define H_    16
#define DH    128
#define ROWS  (L_*NB)        // 4096
#define WELEM (I_*E_)        // 4194304

// ---------------------------------------------------------------------------
// Scratch (device globals — no allocations allowed)
// ---------------------------------------------------------------------------
__device__ __nv_bfloat16 g_Ahi[(size_t)ROWS * I_];  // GEMM A input (split hi)
__device__ __nv_bfloat16 g_Alo[(size_t)ROWS * I_];  // GEMM A input (split lo)
__device__ __nv_bfloat16 g_Qh[(size_t)ROWS * I_];
__device__ __nv_bfloat16 g_Ql[(size_t)ROWS * I_];
__device__ __nv_bfloat16 g_Kh[(size_t)ROWS * I_];
__device__ __nv_bfloat16 g_Kl[(size_t)ROWS * I_];
__device__ __nv_bfloat16 g_Vh[(size_t)ROWS * I_];
__device__ __nv_bfloat16 g_Vl[(size_t)ROWS * I_];
__device__ __nv_bfloat16 g_Whi[(size_t)4 * WELEM];
__device__ __nv_bfloat16 g_Wlo[(size_t)4 * WELEM];

// ---------------------------------------------------------------------------
// PTX helpers (sm_80-era ISA only)
// ---------------------------------------------------------------------------
static __device__ __forceinline__ uint32_t smem_u32(const void* p) {
    uint32_t a;
    asm("{ .reg .u64 t; cvta.to.shared.u64 t, %1; cvt.u32.u64 %0, t; }"
        : "=r"(a) : "l"(p));
    return a;
}
static __device__ __forceinline__ void cp_async16(uint32_t dst, const void* src) {
    asm volatile("cp.async.cg.shared.global [%0], [%1], 16;" :: "r"(dst), "l"(src));
}
static __device__ __forceinline__ void cp_commit() {
    asm volatile("cp.async.commit_group;");
}
static __device__ __forceinline__ void cp_wait1() {
    asm volatile("cp.async.wait_group 1;" ::: "memory");
}
static __device__ __forceinline__ void cp_wait0() {
    asm volatile("cp.async.wait_group 0;" ::: "memory");
}
static __device__ __forceinline__ void ldm_x4(uint32_t& r0, uint32_t& r1,
                                              uint32_t& r2, uint32_t& r3, uint32_t a) {
    asm volatile("ldmatrix.sync.aligned.m8n8.x4.shared.b16 {%0,%1,%2,%3}, [%4];"
                 : "=r"(r0), "=r"(r1), "=r"(r2), "=r"(r3) : "r"(a));
}
static __device__ __forceinline__ void ldm_x4_t(uint32_t& r0, uint32_t& r1,
                                                uint32_t& r2, uint32_t& r3, uint32_t a) {
    asm volatile("ldmatrix.sync.aligned.m8n8.x4.trans.shared.b16 {%0,%1,%2,%3}, [%4];"
                 : "=r"(r0), "=r"(r1), "=r"(r2), "=r"(r3) : "r"(a));
}
static __device__ __forceinline__ void mma_bf16(float* d, const uint32_t* a,
                                                const uint32_t* b) {
    asm volatile(
        "mma.sync.aligned.m16n8k16.row.col.f32.bf16.bf16.f32 "
        "{%0,%1,%2,%3}, {%4,%5,%6,%7}, {%8,%9}, {%0,%1,%2,%3};"
        : "+f"(d[0]), "+f"(d[1]), "+f"(d[2]), "+f"(d[3])
        : "r"(a[0]), "r"(a[1]), "r"(a[2]), "r"(a[3]), "r"(b[0]), "r"(b[1]));
}
static __device__ __forceinline__ uint32_t pack_hi(float x, float y,
                                                   float& rx, float& ry) {
    __nv_bfloat16 hx = __float2bfloat16(x);
    __nv_bfloat16 hy = __float2bfloat16(y);
    rx = x - __bfloat162float(hx);
    ry = y - __bfloat162float(hy);
    __nv_bfloat162 t = __halves2bfloat162(hx, hy);
    return *reinterpret_cast<uint32_t*>(&t);
}
static __device__ __forceinline__ uint32_t pack_bf2(float x, float y) {
    __nv_bfloat162 t = __halves2bfloat162(__float2bfloat16(x), __float2bfloat16(y));
    return *reinterpret_cast<uint32_t*>(&t);
}

// ---------------------------------------------------------------------------
// fp32 -> (hi, lo) bf16 split. dst_tag: 0 -> g_Ahi/g_Alo (query), 1..4 -> weights
// ---------------------------------------------------------------------------
__global__ __launch_bounds__(256) void split_fp32(
    const float* __restrict__ src, int dst_tag, int n)
{
    __nv_bfloat16 *hi, *lo;
    if (dst_tag == 0) { hi = g_Ahi; lo = g_Alo; }
    else {
        hi = g_Whi + (size_t)(dst_tag - 1) * WELEM;
        lo = g_Wlo + (size_t)(dst_tag - 1) * WELEM;
    }
    int i = blockIdx.x * blockDim.x + threadIdx.x;
    int stride = gridDim.x * blockDim.x;
    for (; 4 * i < n; i += stride) {
        float4 v = ((const float4*)src)[i];
        float lx, ly, lz, lw;
        uint32_t h0 = pack_hi(v.x, v.y, lx, ly);
        uint32_t h1 = pack_hi(v.z, v.w, lz, lw);
        uint32_t l0 = pack_bf2(lx, ly);
        uint32_t l1 = pack_bf2(lz, lw);
        ((uint32_t*)(hi + (size_t)4 * i))[0] = h0;
        ((uint32_t*)(hi + (size_t)4 * i))[1] = h1;
        ((uint32_t*)(lo + (size_t)4 * i))[0] = l0;
        ((uint32_t*)(lo + (size_t)4 * i))[1] = l1;
    }
}

// ---------------------------------------------------------------------------
// Split-bf16 GEMM on mma.sync (unchanged core, new epilogue modes):
// out_tag 0/1/2 -> split-bf16 to (Qh,Ql)/(Kh,Kl)/(Vh,Vl); 3 -> fp32 to Copt.
// ---------------------------------------------------------------------------
#define BSTR   24            // halves per smem row (16 data + 8 pad)
#define TILE_B (128*BSTR*2)  // 6144 bytes per tile
#define STG_B  (4*TILE_B)    // 24576 bytes per stage

__global__ __launch_bounds__(256) void gemm_mma(
    int w_idx, const float* __restrict__ bias,
    float* __restrict__ Copt, int out_tag, float alpha)
{
    extern __shared__ __align__(16) char smem[];
    const uint32_t sbase = smem_u32(smem);

    const int tid  = threadIdx.x;
    const int wid  = tid >> 5;
    const int lane = tid & 31;
    const int wm = wid >> 2;
    const int wn = wid & 3;
    const int bm = blockIdx.y * 128;
    const int bn = blockIdx.x * 128;

    const __nv_bfloat16* Bhi = g_Whi + (size_t)w_idx * WELEM;
    const __nv_bfloat16* Blo = g_Wlo + (size_t)w_idx * WELEM;

    int lrow[4], lhalf[4], ltile[4]; uint32_t ldst[4];
#pragma unroll
    for (int t = 0; t < 4; t++) {
        int idx = tid + t * 256;
        ltile[t] = idx >> 8;
        lrow[t]  = (idx >> 1) & 127;
        lhalf[t] = idx & 1;
        ldst[t]  = (uint32_t)(ltile[t] * TILE_B + lrow[t] * (BSTR * 2) + lhalf[t] * 16);
    }
    const __nv_bfloat16* lsrc[4];
#pragma unroll
    for (int t = 0; t < 4; t++) {
        const __nv_bfloat16* base =
            (ltile[t] == 0) ? g_Ahi : (ltile[t] == 1) ? g_Alo : (ltile[t] == 2) ? Bhi : Blo;
        int row = (ltile[t] < 2 ? bm : bn) + lrow[t];
        lsrc[t] = base + (size_t)row * 2048 + lhalf[t] * 8;
    }

    const int frow = lane & 15;
    const int fhal = lane >> 4;
    const uint32_t a_base = (uint32_t)((wm * 64 + frow) * (BSTR * 2) + fhal * 16);
    const uint32_t b_base = (uint32_t)((wn * 32 + frow) * (BSTR * 2) + fhal * 16);

    float acc[4][4][4];
#pragma unroll
    for (int i = 0; i < 4; i++)
#pragma unroll
        for (int j = 0; j < 4; j++)
#pragma unroll
            for (int q = 0; q < 4; q++) acc[i][j][q] = 0.0f;

#pragma unroll
    for (int t = 0; t < 4; t++)
        cp_async16(sbase + ldst[t], lsrc[t]);
    cp_commit();

    for (int s = 0; s < 128; s++) {
        if (s + 1 < 128) {
            const uint32_t stg = (uint32_t)(((s + 1) & 1) * STG_B);
#pragma unroll
            for (int t = 0; t < 4; t++)
                cp_async16(sbase + stg + ldst[t], lsrc[t] + (s + 1) * 16);
            cp_commit();
            cp_wait1();
        } else {
            cp_wait0();
        }
        __syncthreads();

        const uint32_t stg = sbase + (uint32_t)((s & 1) * STG_B);

        uint32_t bh[4][2], bl[4][2];
#pragma unroll
        for (int pair = 0; pair < 2; pair++) {
            uint32_t r0, r1, r2, r3;
            ldm_x4(r0, r1, r2, r3, stg + 2 * TILE_B + b_base + (uint32_t)(pair * 16 * BSTR * 2));
            bh[2 * pair][0] = r0; bh[2 * pair][1] = r2;
            bh[2 * pair + 1][0] = r1; bh[2 * pair + 1][1] = r3;
            ldm_x4(r0, r1, r2, r3, stg + 3 * TILE_B + b_base + (uint32_t)(pair * 16 * BSTR * 2));
            bl[2 * pair][0] = r0; bl[2 * pair][1] = r2;
            bl[2 * pair + 1][0] = r1; bl[2 * pair + 1][1] = r3;
        }

#pragma unroll
        for (int mf = 0; mf < 4; mf++) {
            uint32_t ah[4], al[4];
            ldm_x4(ah[0], ah[1], ah[2], ah[3],
                   stg + a_base + (uint32_t)(mf * 16 * BSTR * 2));
            ldm_x4(al[0], al[1], al[2], al[3],
                   stg + TILE_B + a_base + (uint32_t)(mf * 16 * BSTR * 2));
#pragma unroll
            for (int nf = 0; nf < 4; nf++) {
                mma_bf16(acc[mf][nf], ah, bh[nf]);
                mma_bf16(acc[mf][nf], ah, bl[nf]);
                mma_bf16(acc[mf][nf], al, bh[nf]);
            }
        }
        __syncthreads();
    }

    // Epilogue
    if (out_tag == 3) {
#pragma unroll
        for (int mf = 0; mf < 4; mf++) {
#pragma unroll
            for (int nf = 0; nf < 4; nf++) {
                const int row0 = bm + wm * 64 + mf * 16 + (lane >> 2);
                const int col  = bn + wn * 32 + nf * 8 + (lane & 3) * 2;
                float2 bv = *(const float2*)&bias[col];
                float2 o0, o1;
                o0.x = alpha * (acc[mf][nf][0] + bv.x);
                o0.y = alpha * (acc[mf][nf][1] + bv.y);
                o1.x = alpha * (acc[mf][nf][2] + bv.x);
                o1.y = alpha * (acc[mf][nf][3] + bv.y);
                *(float2*)&Copt[(size_t)row0 * 2048 + col] = o0;
                *(float2*)&Copt[(size_t)(row0 + 8) * 2048 + col] = o1;
            }
        }
    } else {
        __nv_bfloat16* ho = (out_tag == 0) ? g_Qh : (out_tag == 1) ? g_Kh : g_Vh;
        __nv_bfloat16* lo = (out_tag == 0) ? g_Ql : (out_tag == 1) ? g_Kl : g_Vl;
#pragma unroll
        for (int mf = 0; mf < 4; mf++) {
#pragma unroll
            for (int nf = 0; nf < 4; nf++) {
                const int row0 = bm + wm * 64 + mf * 16 + (lane >> 2);
                const int col  = bn + wn * 32 + nf * 8 + (lane & 3) * 2;
                float2 bv = *(const float2*)&bias[col];
                float x0 = alpha * (acc[mf][nf][0] + bv.x);
                float y0 = alpha * (acc[mf][nf][1] + bv.y);
                float x1 = alpha * (acc[mf][nf][2] + bv.x);
                float y1 = alpha * (acc[mf][nf][3] + bv.y);
                float lx, ly;
                uint32_t h0 = pack_hi(x0, y0, lx, ly);
                uint32_t l0 = pack_bf2(lx, ly);
                *(uint32_t*)&ho[(size_t)row0 * 2048 + col] = h0;
                *(uint32_t*)&lo[(size_t)row0 * 2048 + col] = l0;
                uint32_t h1 = pack_hi(x1, y1, lx, ly);
                uint32_t l1 = pack_bf2(lx, ly);
                *(uint32_t*)&ho[(size_t)(row0 + 8) * 2048 + col] = h1;
                *(uint32_t*)&lo[(size_t)(row0 + 8) * 2048 + col] = l1;
            }
        }
    }
}

// ---------------------------------------------------------------------------
// HMMA causal flash attention, split-bf16, 128 threads (4 warps).
// Warp = 16 q-rows; CTA = 64 q-rows x full causal range, Bk=32, d=128.
// Q frags in regs (from gmem). K/V tiles in smem (272B row stride).
// Output written as split bf16 directly into g_Ahi/g_Alo (out-proj A input).
// ---------------------------------------------------------------------------
#define ASR 272                     // smem row stride in bytes (136 halves)
#define AKH 0
#define AKL 8704
#define AVH 17408
#define AVL 26112
#define ATT_SMEM 34816

__global__ __launch_bounds__(128, 1) void flash_attn_mma()
{
    extern __shared__ __align__(16) char smem[];
    const uint32_t sb = smem_u32(smem);
    const int tid  = threadIdx.x;
    const int wid  = tid >> 5;
    const int lane = tid & 31;
    const int qt = blockIdx.x;
    const int bb = blockIdx.y;
    const int n  = bb / H_;
    const int h  = bb % H_;
    const int q0 = qt * 64;
    const int wr = q0 + wid * 16;       // warp's q-row base
    const int colbase = h * DH;
    const int lr = lane >> 2;
    const int lc = lane & 3;

    // Q fragments (hi, lo) directly from gmem: A layout m16k16.
    uint32_t qfh[8][4], qfl[8][4];
    {
        const size_t base0 = ((size_t)(wr + lr) * NB + n) * 2048 + colbase;
        const size_t base1 = ((size_t)(wr + lr + 8) * NB + n) * 2048 + colbase;
#pragma unroll
        for (int t = 0; t < 8; t++) {
            const int k = 16 * t + 2 * lc;
            qfh[t][0] = *(const uint32_t*)&g_Qh[base0 + k];
            qfh[t][1] = *(const uint32_t*)&g_Qh[base1 + k];
            qfh[t][2] = *(const uint32_t*)&g_Qh[base0 + k + 8];
            qfh[t][3] = *(const uint32_t*)&g_Qh[base1 + k + 8];
            qfl[t][0] = *(const uint32_t*)&g_Ql[base0 + k];
            qfl[t][1] = *(const uint32_t*)&g_Ql[base1 + k];
            qfl[t][2] = *(const uint32_t*)&g_Ql[base0 + k + 8];
            qfl[t][3] = *(const uint32_t*)&g_Ql[base1 + k + 8];
        }
    }

    float oacc[16][4];
#pragma unroll
    for (int f = 0; f < 16; f++)
#pragma unroll
        for (int q = 0; q < 4; q++) oacc[f][q] = 0.0f;
    float m_run[2] = {-1e30f, -1e30f};
    float l_run[2] = {0.0f, 0.0f};

    const int jt_max = 2 * qt + 1;
    for (int jt = 0; jt <= jt_max; jt++) {
        const int k0 = jt * 32;
        __syncthreads();   // previous tile's smem readers done
        // Fill K/V tiles (hi+lo): 2048 x 16B chunks, 16 per thread.
#pragma unroll
        for (int i = 0; i < 16; i++) {
            int c = tid + i * 128;
            int reg = c >> 9;
            int idx = c & 511;
            int row = idx >> 4;
            int seg = idx & 15;
            uint32_t dst = sb + reg * 8704 + row * ASR + seg * 16;
            const __nv_bfloat16* src =
                (reg == 0) ? g_Kh : (reg == 1) ? g_Kl : (reg == 2) ? g_Vh : g_Vl;
            cp_async16(dst, src + ((size_t)(k0 + row) * NB + n) * 2048 + colbase + seg * 8);
        }
        cp_commit();
        cp_wait0();
        __syncthreads();

        if (k0 > wr + 15) continue;   // tile fully masked for this warp

        // --- S = Q K^T (3 split products) ---
        float sacc[4][4];
#pragma unroll
        for (int j = 0; j < 4; j++)
#pragma unroll
            for (int q = 0; q < 4; q++) sacc[j][q] = 0.0f;

#pragma unroll
        for (int t = 0; t < 8; t++) {
            uint32_t kh[4][2], kl[4][2];
#pragma unroll
            for (int g = 0; g < 2; g++) {
                uint32_t row = (uint32_t)((lane & 7) + ((lane >> 4) << 3) + 16 * g);
                uint32_t a = sb + row * ASR + 32 * t + (((lane >> 3) & 1) << 4);
                uint32_t r0, r1, r2, r3;
                ldm_x4(r0, r1, r2, r3, a);
                kh[2 * g][0] = r0; kh[2 * g][1] = r1;
                kh[2 * g + 1][0] = r2; kh[2 * g + 1][1] = r3;
                ldm_x4(r0, r1, r2, r3, a + AKL);
                kl[2 * g][0] = r0; kl[2 * g][1] = r1;
                kl[2 * g + 1][0] = r2; kl[2 * g + 1][1] = r3;
            }
#pragma unroll
            for (int j = 0; j < 4; j++) {
                mma_bf16(sacc[j], qfh[t], kh[j]);
                mma_bf16(sacc[j], qfh[t], kl[j]);
                mma_bf16(sacc[j], qfl[t], kh[j]);
            }
        }

        // --- causal mask ---
        if (k0 + 31 > wr) {
            const int r0a = wr + lr, r1a = r0a + 8;
#pragma unroll
            for (int j = 0; j < 4; j++) {
                int kc = k0 + 8 * j + 2 * lc;
                if (kc > r0a)     sacc[j][0] = -1e30f;
                if (kc + 1 > r0a) sacc[j][1] = -1e30f;
                if (kc > r1a)     sacc[j][2] = -1e30f;
                if (kc + 1 > r1a) sacc[j][3] = -1e30f;
            }
        }

        // --- online softmax (rows: lr and lr+8; reduce over lanes xor 1,2) ---
#pragma unroll
        for (int r = 0; r < 2; r++) {
            float mt = -1e30f;
#pragma unroll
            for (int j = 0; j < 4; j++)
                mt = fmaxf(mt, fmaxf(sacc[j][2 * r], sacc[j][2 * r + 1]));
            mt = fmaxf(mt, __shfl_xor_sync(0xffffffffu, mt, 1));
            mt = fmaxf(mt, __shfl_xor_sync(0xffffffffu, mt, 2));
            float mnew = fmaxf(m_run[r], mt);
            float corr = __expf(m_run[r] - mnew);
            m_run[r] = mnew;
            float rs = 0.0f;
#pragma unroll
            for (int j = 0; j < 4; j++) {
                sacc[j][2 * r]     = __expf(sacc[j][2 * r] - mnew);
                sacc[j][2 * r + 1] = __expf(sacc[j][2 * r + 1] - mnew);
                rs += sacc[j][2 * r] + sacc[j][2 * r + 1];
            }
            rs += __shfl_xor_sync(0xffffffffu, rs, 1);
            rs += __shfl_xor_sync(0xffffffffu, rs, 2);
            l_run[r] = l_run[r] * corr + rs;
#pragma unroll
            for (int f = 0; f < 16; f++) {
                oacc[f][2 * r]     *= corr;
                oacc[f][2 * r + 1] *= corr;
            }
        }

        // --- P fragments (split hi/lo), direct A-operand layout ---
        uint32_t ph[2][4], pl[2][4];
#pragma unroll
        for (int t2 = 0; t2 < 2; t2++) {
            const float* s0 = sacc[2 * t2];
            const float* s1 = sacc[2 * t2 + 1];
            float lx, ly;
            ph[t2][0] = pack_hi(s0[0], s0[1], lx, ly); pl[t2][0] = pack_bf2(lx, ly);
            ph[t2][1] = pack_hi(s0[2], s0[3], lx, ly); pl[t2][1] = pack_bf2(lx, ly);
            ph[t2][2] = pack_hi(s1[0], s1[1], lx, ly); pl[t2][2] = pack_bf2(lx, ly);
            ph[t2][3] = pack_hi(s1[2], s1[3], lx, ly); pl[t2][3] = pack_bf2(lx, ly);
        }

        // --- O += P V (3 split products), V as B via ldmatrix.trans ---
#pragma unroll
        for (int t2 = 0; t2 < 2; t2++) {
            uint32_t row = (uint32_t)((lane & 7) + (((lane >> 3) & 1) << 3) + 16 * t2);
#pragma unroll
            for (int g = 0; g < 8; g++) {
                uint32_t col = (uint32_t)(16 * g + ((lane >> 4) << 3));
                uint32_t a = sb + AVH + row * ASR + col * 2;
                uint32_t r0, r1, r2, r3;
                ldm_x4_t(r0, r1, r2, r3, a);
                uint32_t vh0[2] = {r0, r1}, vh1[2] = {r2, r3};
                ldm_x4_t(r0, r1, r2, r3, a + 8704);
                uint32_t vl0[2] = {r0, r1}, vl1[2] = {r2, r3};
                mma_bf16(oacc[2 * g],     ph[t2], vh0);
                mma_bf16(oacc[2 * g],     ph[t2], vl0);
                mma_bf16(oacc[2 * g],     pl[t2], vh0);
                mma_bf16(oacc[2 * g + 1], ph[t2], vh1);
                mma_bf16(oacc[2 * g + 1], ph[t2], vl1);
                mma_bf16(oacc[2 * g + 1], pl[t2], vh1);
            }
        }
    }

    // --- epilogue: normalize, split to bf16, store to out-proj A buffers ---
    const float inv0 = 1.0f / l_run[0];
    const float inv1 = 1.0f / l_run[1];
    const size_t base0 = ((size_t)(wr + lr) * NB + n) * 2048 + colbase;
    const size_t base1 = ((size_t)(wr + lr + 8) * NB + n) * 2048 + colbase;
#pragma unroll
    for (int f = 0; f < 16; f++) {
        const int c = 8 * f + 2 * lc;
        float lx, ly;
        uint32_t h0 = pack_hi(oacc[f][0] * inv0, oacc[f][1] * inv0, lx, ly);
        uint32_t l0 = pack_bf2(lx, ly);
        *(uint32_t*)&g_Ahi[base0 + c] = h0;
        *(uint32_t*)&g_Alo[base0 + c] = l0;
        uint32_t h1 = pack_hi(oacc[f][2] * inv1, oacc[f][3] * inv1, lx, ly);
        uint32_t l1 = pack_bf2(lx, ly);
        *(uint32_t*)&g_Ahi[base1 + c] = h1;
        *(uint32_t*)&g_Alo[base1 + c] = l1;
    }
}

// ---------------------------------------------------------------------------
// kernel_launch: pure kernel launches only.
// ---------------------------------------------------------------------------
extern "C" void kernel_launch(void* const* d_in, const int* in_sizes, int n_in,
                              void* d_out, int out_size)
{
    (void)in_sizes; (void)n_in; (void)out_size;
    const float* query = (const float*)d_in[0];
    const float* qw    = (const float*)d_in[1];
    const float* qb    = (const float*)d_in[2];
    const float* kw    = (const float*)d_in[3];
    const float* kb    = (const float*)d_in[4];
    const float* vw    = (const float*)d_in[5];
    const float* vb    = (const float*)d_in[6];
    const float* ow    = (const float*)d_in[7];
    const float* ob    = (const float*)d_in[8];
    float* out = (float*)d_out;

    const float scale = 0.08838834764831845f;  // 1/sqrt(128)
    const int nA = ROWS * I_;
    const int nW = WELEM;
    dim3 gg(16, 32);

    split_fp32<<<nA / 1024, 256>>>(query, 0, nA);
    split_fp32<<<nW / 1024, 256>>>(qw, 1, nW);
    split_fp32<<<nW / 1024, 256>>>(kw, 2, nW);
    split_fp32<<<nW / 1024, 256>>>(vw, 3, nW);
    split_fp32<<<nW / 1024, 256>>>(ow, 4, nW);

    // Projections -> split bf16 Q/K/V directly
    gemm_mma<<<gg, 256, 2 * STG_B>>>(0, qb, nullptr, 0, scale);
    gemm_mma<<<gg, 256, 2 * STG_B>>>(1, kb, nullptr, 1, 1.0f);
    gemm_mma<<<gg, 256, 2 * STG_B>>>(2, vb, nullptr, 2, 1.0f);

    // HMMA attention -> writes split bf16 into g_Ahi/g_Alo
    flash_attn_mma<<<dim3(L_ / 64, NB * H_), 128, ATT_SMEM>>>();

    // Output projection (fp32 out)
    gemm_mma<<<gg, 256, 2 * STG_B>>>(3, ob, out, 3, 1.0f);
}

// round 10
// speedup vs baseline: 2.8777x; 1.1627x over previous
// v9: GEMM 3-stage single-barrier pipeline (XOR swizzle, 48KB exact);
//     attention K/V split-wait overlap; fused weight splits.
#include <cuda_runtime.h>
#include <cuda_bf16.h>
#include <stdint.h>
#include <math.h>

#define L_    2048
#define NB    2
#define E_    2048
#define I_    2048
#define H_    16
#define DH    128
#define ROWS  (L_*NB)        // 4096
#define WELEM (I_*E_)        // 4194304

// ---------------------------------------------------------------------------
// Scratch (device globals — no allocations allowed)
// ---------------------------------------------------------------------------
__device__ __nv_bfloat16 g_Ahi[(size_t)ROWS * I_];  // GEMM A input (split hi)
__device__ __nv_bfloat16 g_Alo[(size_t)ROWS * I_];  // GEMM A input (split lo)
__device__ __nv_bfloat16 g_Qh[(size_t)ROWS * I_];
__device__ __nv_bfloat16 g_Ql[(size_t)ROWS * I_];
__device__ __nv_bfloat16 g_Kh[(size_t)ROWS * I_];
__device__ __nv_bfloat16 g_Kl[(size_t)ROWS * I_];
__device__ __nv_bfloat16 g_Vh[(size_t)ROWS * I_];
__device__ __nv_bfloat16 g_Vl[(size_t)ROWS * I_];
__device__ __nv_bfloat16 g_Whi[(size_t)4 * WELEM];
__device__ __nv_bfloat16 g_Wlo[(size_t)4 * WELEM];

// ---------------------------------------------------------------------------
// PTX helpers (sm_80-era ISA only)
// ---------------------------------------------------------------------------
static __device__ __forceinline__ uint32_t smem_u32(const void* p) {
    uint32_t a;
    asm("{ .reg .u64 t; cvta.to.shared.u64 t, %1; cvt.u32.u64 %0, t; }"
        : "=r"(a) : "l"(p));
    return a;
}
static __device__ __forceinline__ void cp_async16(uint32_t dst, const void* src) {
    asm volatile("cp.async.cg.shared.global [%0], [%1], 16;" :: "r"(dst), "l"(src));
}
static __device__ __forceinline__ void cp_commit() {
    asm volatile("cp.async.commit_group;");
}
static __device__ __forceinline__ void cp_wait1() {
    asm volatile("cp.async.wait_group 1;" ::: "memory");
}
static __device__ __forceinline__ void cp_wait0() {
    asm volatile("cp.async.wait_group 0;" ::: "memory");
}
static __device__ __forceinline__ void ldm_x4(uint32_t& r0, uint32_t& r1,
                                              uint32_t& r2, uint32_t& r3, uint32_t a) {
    asm volatile("ldmatrix.sync.aligned.m8n8.x4.shared.b16 {%0,%1,%2,%3}, [%4];"
                 : "=r"(r0), "=r"(r1), "=r"(r2), "=r"(r3) : "r"(a));
}
static __device__ __forceinline__ void ldm_x4_t(uint32_t& r0, uint32_t& r1,
                                                uint32_t& r2, uint32_t& r3, uint32_t a) {
    asm volatile("ldmatrix.sync.aligned.m8n8.x4.trans.shared.b16 {%0,%1,%2,%3}, [%4];"
                 : "=r"(r0), "=r"(r1), "=r"(r2), "=r"(r3) : "r"(a));
}
static __device__ __forceinline__ void mma_bf16(float* d, const uint32_t* a,
                                                const uint32_t* b) {
    asm volatile(
        "mma.sync.aligned.m16n8k16.row.col.f32.bf16.bf16.f32 "
        "{%0,%1,%2,%3}, {%4,%5,%6,%7}, {%8,%9}, {%0,%1,%2,%3};"
        : "+f"(d[0]), "+f"(d[1]), "+f"(d[2]), "+f"(d[3])
        : "r"(a[0]), "r"(a[1]), "r"(a[2]), "r"(a[3]), "r"(b[0]), "r"(b[1]));
}
static __device__ __forceinline__ uint32_t pack_hi(float x, float y,
                                                   float& rx, float& ry) {
    __nv_bfloat16 hx = __float2bfloat16(x);
    __nv_bfloat16 hy = __float2bfloat16(y);
    rx = x - __bfloat162float(hx);
    ry = y - __bfloat162float(hy);
    __nv_bfloat162 t = __halves2bfloat162(hx, hy);
    return *reinterpret_cast<uint32_t*>(&t);
}
static __device__ __forceinline__ uint32_t pack_bf2(float x, float y) {
    __nv_bfloat162 t = __halves2bfloat162(__float2bfloat16(x), __float2bfloat16(y));
    return *reinterpret_cast<uint32_t*>(&t);
}

// ---------------------------------------------------------------------------
// fp32 -> (hi, lo) bf16 splits
// ---------------------------------------------------------------------------
__global__ __launch_bounds__(256) void split_query(const float* __restrict__ src, int n)
{
    int i = blockIdx.x * blockDim.x + threadIdx.x;
    int stride = gridDim.x * blockDim.x;
    for (; 4 * i < n; i += stride) {
        float4 v = ((const float4*)src)[i];
        float lx, ly, lz, lw;
        uint32_t h0 = pack_hi(v.x, v.y, lx, ly);
        uint32_t h1 = pack_hi(v.z, v.w, lz, lw);
        ((uint32_t*)(g_Ahi + (size_t)4 * i))[0] = h0;
        ((uint32_t*)(g_Ahi + (size_t)4 * i))[1] = h1;
        ((uint32_t*)(g_Alo + (size_t)4 * i))[0] = pack_bf2(lx, ly);
        ((uint32_t*)(g_Alo + (size_t)4 * i))[1] = pack_bf2(lz, lw);
    }
}

__global__ __launch_bounds__(256) void split_weights(
    const float* __restrict__ qw, const float* __restrict__ kw,
    const float* __restrict__ vw, const float* __restrict__ ow)
{
    const int w = blockIdx.y;
    const float* src = (w == 0) ? qw : (w == 1) ? kw : (w == 2) ? vw : ow;
    __nv_bfloat16* hi = g_Whi + (size_t)w * WELEM;
    __nv_bfloat16* lo = g_Wlo + (size_t)w * WELEM;
    int i = blockIdx.x * blockDim.x + threadIdx.x;
    int stride = gridDim.x * blockDim.x;
    for (; 4 * i < WELEM; i += stride) {
        float4 v = ((const float4*)src)[i];
        float lx, ly, lz, lw;
        uint32_t h0 = pack_hi(v.x, v.y, lx, ly);
        uint32_t h1 = pack_hi(v.z, v.w, lz, lw);
        ((uint32_t*)(hi + (size_t)4 * i))[0] = h0;
        ((uint32_t*)(hi + (size_t)4 * i))[1] = h1;
        ((uint32_t*)(lo + (size_t)4 * i))[0] = pack_bf2(lx, ly);
        ((uint32_t*)(lo + (size_t)4 * i))[1] = pack_bf2(lz, lw);
    }
}

// ---------------------------------------------------------------------------
// Split-bf16 GEMM, 3-stage single-barrier pipeline, XOR-swizzled smem.
// Tile 128x128, BK=16. Stage = 4 sub-tiles (Ahi,Alo,Bhi,Blo) of
// 128 rows x 32B packed; chunk index XOR-swizzled by (row>>2)&1 so each
// ldmatrix phase's 8 addresses hit 8 distinct 16B slots mod 128B.
// Smem = 3 * 16384 = 49152 B exactly (no opt-in attribute).
// out_tag 0/1/2 -> split-bf16 (Qh,Ql)/(Kh,Kl)/(Vh,Vl); 3 -> fp32 Copt.
// ---------------------------------------------------------------------------
#define TIL2 4096            // bytes per sub-tile (128 rows x 32B)
#define STG2 16384           // bytes per stage

__global__ __launch_bounds__(256) void gemm_mma(
    int w_idx, const float* __restrict__ bias,
    float* __restrict__ Copt, int out_tag, float alpha)
{
    extern __shared__ __align__(16) char smem[];
    const uint32_t sbase = smem_u32(smem);

    const int tid  = threadIdx.x;
    const int wid  = tid >> 5;
    const int lane = tid & 31;
    const int wm = wid >> 2;
    const int wn = wid & 3;
    const int bm = blockIdx.y * 128;
    const int bn = blockIdx.x * 128;

    const __nv_bfloat16* Bhi = g_Whi + (size_t)w_idx * WELEM;
    const __nv_bfloat16* Blo = g_Wlo + (size_t)w_idx * WELEM;

    // Loader: thread handles one (row, chunk) across all 4 sub-tiles.
    const int lrow = tid >> 1;
    const int lch  = tid & 1;
    const uint32_t swo = (uint32_t)(lrow * 32 + ((lch ^ ((lrow >> 2) & 1)) * 16));
    const __nv_bfloat16* srcAh = g_Ahi + (size_t)(bm + lrow) * 2048 + lch * 8;
    const __nv_bfloat16* srcAl = g_Alo + (size_t)(bm + lrow) * 2048 + lch * 8;
    const __nv_bfloat16* srcBh = Bhi   + (size_t)(bn + lrow) * 2048 + lch * 8;
    const __nv_bfloat16* srcBl = Blo   + (size_t)(bn + lrow) * 2048 + lch * 8;

    // Fragment addressing
    const int frow = lane & 15;
    const int fhal = lane >> 4;
    const uint32_t fswz = (uint32_t)(((fhal ^ ((frow >> 2) & 1)) * 16));
    const uint32_t a_off = (uint32_t)((wm * 64 + frow) * 32) + fswz;
    const uint32_t b_off = (uint32_t)((wn * 32 + frow) * 32) + fswz;

    float acc[4][4][4];
#pragma unroll
    for (int i = 0; i < 4; i++)
#pragma unroll
        for (int j = 0; j < 4; j++)
#pragma unroll
            for (int q = 0; q < 4; q++) acc[i][j][q] = 0.0f;

    // Prologue: stages 0, 1
#pragma unroll
    for (int ps = 0; ps < 2; ps++) {
        const uint32_t stg = sbase + (uint32_t)(ps * STG2);
        cp_async16(stg + 0 * TIL2 + swo, srcAh + ps * 16);
        cp_async16(stg + 1 * TIL2 + swo, srcAl + ps * 16);
        cp_async16(stg + 2 * TIL2 + swo, srcBh + ps * 16);
        cp_async16(stg + 3 * TIL2 + swo, srcBl + ps * 16);
        cp_commit();
    }

    int cur = 0;  // s % 3
    for (int s = 0; s < 128; s++) {
        if (s < 127) cp_wait1(); else cp_wait0();
        __syncthreads();

        if (s + 2 < 128) {
            int nxt2 = cur + 2; if (nxt2 >= 3) nxt2 -= 3;
            const uint32_t stg = sbase + (uint32_t)(nxt2 * STG2);
            cp_async16(stg + 0 * TIL2 + swo, srcAh + (s + 2) * 16);
            cp_async16(stg + 1 * TIL2 + swo, srcAl + (s + 2) * 16);
            cp_async16(stg + 2 * TIL2 + swo, srcBh + (s + 2) * 16);
            cp_async16(stg + 3 * TIL2 + swo, srcBl + (s + 2) * 16);
            cp_commit();
        }

        const uint32_t stg = sbase + (uint32_t)(cur * STG2);
        cur++; if (cur == 3) cur = 0;

        uint32_t bh[4][2], bl[4][2];
#pragma unroll
        for (int pair = 0; pair < 2; pair++) {
            uint32_t r0, r1, r2, r3;
            ldm_x4(r0, r1, r2, r3, stg + 2 * TIL2 + b_off + (uint32_t)(pair * 512));
            bh[2 * pair][0] = r0; bh[2 * pair][1] = r2;
            bh[2 * pair + 1][0] = r1; bh[2 * pair + 1][1] = r3;
            ldm_x4(r0, r1, r2, r3, stg + 3 * TIL2 + b_off + (uint32_t)(pair * 512));
            bl[2 * pair][0] = r0; bl[2 * pair][1] = r2;
            bl[2 * pair + 1][0] = r1; bl[2 * pair + 1][1] = r3;
        }

#pragma unroll
        for (int mf = 0; mf < 4; mf++) {
            uint32_t ah[4], al[4];
            ldm_x4(ah[0], ah[1], ah[2], ah[3], stg + a_off + (uint32_t)(mf * 512));
            ldm_x4(al[0], al[1], al[2], al[3], stg + TIL2 + a_off + (uint32_t)(mf * 512));
#pragma unroll
            for (int nf = 0; nf < 4; nf++) {
                mma_bf16(acc[mf][nf], ah, bh[nf]);
                mma_bf16(acc[mf][nf], ah, bl[nf]);
                mma_bf16(acc[mf][nf], al, bh[nf]);
            }
        }
    }

    // Epilogue
    if (out_tag == 3) {
#pragma unroll
        for (int mf = 0; mf < 4; mf++) {
#pragma unroll
            for (int nf = 0; nf < 4; nf++) {
                const int row0 = bm + wm * 64 + mf * 16 + (lane >> 2);
                const int col  = bn + wn * 32 + nf * 8 + (lane & 3) * 2;
                float2 bv = *(const float2*)&bias[col];
                float2 o0, o1;
                o0.x = alpha * (acc[mf][nf][0] + bv.x);
                o0.y = alpha * (acc[mf][nf][1] + bv.y);
                o1.x = alpha * (acc[mf][nf][2] + bv.x);
                o1.y = alpha * (acc[mf][nf][3] + bv.y);
                *(float2*)&Copt[(size_t)row0 * 2048 + col] = o0;
                *(float2*)&Copt[(size_t)(row0 + 8) * 2048 + col] = o1;
            }
        }
    } else {
        __nv_bfloat16* ho = (out_tag == 0) ? g_Qh : (out_tag == 1) ? g_Kh : g_Vh;
        __nv_bfloat16* lo = (out_tag == 0) ? g_Ql : (out_tag == 1) ? g_Kl : g_Vl;
#pragma unroll
        for (int mf = 0; mf < 4; mf++) {
#pragma unroll
            for (int nf = 0; nf < 4; nf++) {
                const int row0 = bm + wm * 64 + mf * 16 + (lane >> 2);
                const int col  = bn + wn * 32 + nf * 8 + (lane & 3) * 2;
                float2 bv = *(const float2*)&bias[col];
                float x0 = alpha * (acc[mf][nf][0] + bv.x);
                float y0 = alpha * (acc[mf][nf][1] + bv.y);
                float x1 = alpha * (acc[mf][nf][2] + bv.x);
                float y1 = alpha * (acc[mf][nf][3] + bv.y);
                float lx, ly;
                uint32_t h0 = pack_hi(x0, y0, lx, ly);
                uint32_t l0 = pack_bf2(lx, ly);
                *(uint32_t*)&ho[(size_t)row0 * 2048 + col] = h0;
                *(uint32_t*)&lo[(size_t)row0 * 2048 + col] = l0;
                uint32_t h1 = pack_hi(x1, y1, lx, ly);
                uint32_t l1 = pack_bf2(lx, ly);
                *(uint32_t*)&ho[(size_t)(row0 + 8) * 2048 + col] = h1;
                *(uint32_t*)&lo[(size_t)(row0 + 8) * 2048 + col] = l1;
            }
        }
    }
}

// ---------------------------------------------------------------------------
// HMMA causal flash attention, split-bf16, 128 threads (4 warps).
// K and V loaded as separate cp.async commit groups: QK^T overlaps V load.
// ---------------------------------------------------------------------------
#define ASR 272                     // smem row stride bytes (136 halves)
#define AKL 8704
#define AVH 17408
#define ATT_SMEM 34816

__global__ __launch_bounds__(128, 1) void flash_attn_mma()
{
    extern __shared__ __align__(16) char smem[];
    const uint32_t sb = smem_u32(smem);
    const int tid  = threadIdx.x;
    const int wid  = tid >> 5;
    const int lane = tid & 31;
    const int qt = blockIdx.x;
    const int bb = blockIdx.y;
    const int n  = bb / H_;
    const int h  = bb % H_;
    const int q0 = qt * 64;
    const int wr = q0 + wid * 16;
    const int colbase = h * DH;
    const int lr = lane >> 2;
    const int lc = lane & 3;

    // Q fragments (hi, lo) direct from gmem (A layout m16k16)
    uint32_t qfh[8][4], qfl[8][4];
    {
        const size_t base0 = ((size_t)(wr + lr) * NB + n) * 2048 + colbase;
        const size_t base1 = ((size_t)(wr + lr + 8) * NB + n) * 2048 + colbase;
#pragma unroll
        for (int t = 0; t < 8; t++) {
            const int k = 16 * t + 2 * lc;
            qfh[t][0] = *(const uint32_t*)&g_Qh[base0 + k];
            qfh[t][1] = *(const uint32_t*)&g_Qh[base1 + k];
            qfh[t][2] = *(const uint32_t*)&g_Qh[base0 + k + 8];
            qfh[t][3] = *(const uint32_t*)&g_Qh[base1 + k + 8];
            qfl[t][0] = *(const uint32_t*)&g_Ql[base0 + k];
            qfl[t][1] = *(const uint32_t*)&g_Ql[base1 + k];
            qfl[t][2] = *(const uint32_t*)&g_Ql[base0 + k + 8];
            qfl[t][3] = *(const uint32_t*)&g_Ql[base1 + k + 8];
        }
    }

    float oacc[16][4];
#pragma unroll
    for (int f = 0; f < 16; f++)
#pragma unroll
        for (int q = 0; q < 4; q++) oacc[f][q] = 0.0f;
    float m_run[2] = {-1e30f, -1e30f};
    float l_run[2] = {0.0f, 0.0f};

    const int jt_max = 2 * qt + 1;
    for (int jt = 0; jt <= jt_max; jt++) {
        const int k0 = jt * 32;
        __syncthreads();   // prior tile's readers done (K and V)

        // Group 1: K tiles (hi+lo) — 1024 chunks, 8/thread
#pragma unroll
        for (int i = 0; i < 8; i++) {
            int c = tid + i * 128;
            int reg = c >> 9;              // 0: Kh, 1: Kl
            int idx = c & 511;
            int row = idx >> 4;
            int seg = idx & 15;
            uint32_t dst = sb + reg * 8704 + row * ASR + seg * 16;
            const __nv_bfloat16* src = (reg == 0) ? g_Kh : g_Kl;
            cp_async16(dst, src + ((size_t)(k0 + row) * NB + n) * 2048 + colbase + seg * 8);
        }
        cp_commit();
        // Group 2: V tiles (hi+lo)
#pragma unroll
        for (int i = 0; i < 8; i++) {
            int c = tid + i * 128;
            int reg = c >> 9;              // 0: Vh, 1: Vl
            int idx = c & 511;
            int row = idx >> 4;
            int seg = idx & 15;
            uint32_t dst = sb + AVH + reg * 8704 + row * ASR + seg * 16;
            const __nv_bfloat16* src = (reg == 0) ? g_Vh : g_Vl;
            cp_async16(dst, src + ((size_t)(k0 + row) * NB + n) * 2048 + colbase + seg * 8);
        }
        cp_commit();

        cp_wait1();        // K ready (V may still be in flight)
        __syncthreads();

        const bool active = (k0 <= wr + 15);
        float sacc[4][4];
        uint32_t ph[2][4], pl[2][4];

        if (active) {
#pragma unroll
            for (int j = 0; j < 4; j++)
#pragma unroll
                for (int q = 0; q < 4; q++) sacc[j][q] = 0.0f;

#pragma unroll
            for (int t = 0; t < 8; t++) {
                uint32_t kh[4][2], kl[4][2];
#pragma unroll
                for (int g = 0; g < 2; g++) {
                    uint32_t row = (uint32_t)((lane & 7) + ((lane >> 4) << 3) + 16 * g);
                    uint32_t a = sb + row * ASR + 32 * t + (((lane >> 3) & 1) << 4);
                    uint32_t r0, r1, r2, r3;
                    ldm_x4(r0, r1, r2, r3, a);
                    kh[2 * g][0] = r0; kh[2 * g][1] = r1;
                    kh[2 * g + 1][0] = r2; kh[2 * g + 1][1] = r3;
                    ldm_x4(r0, r1, r2, r3, a + AKL);
                    kl[2 * g][0] = r0; kl[2 * g][1] = r1;
                    kl[2 * g + 1][0] = r2; kl[2 * g + 1][1] = r3;
                }
#pragma unroll
                for (int j = 0; j < 4; j++) {
                    mma_bf16(sacc[j], qfh[t], kh[j]);
                    mma_bf16(sacc[j], qfh[t], kl[j]);
                    mma_bf16(sacc[j], qfl[t], kh[j]);
                }
            }

            if (k0 + 31 > wr) {
                const int r0a = wr + lr, r1a = r0a + 8;
#pragma unroll
                for (int j = 0; j < 4; j++) {
                    int kc = k0 + 8 * j + 2 * lc;
                    if (kc > r0a)     sacc[j][0] = -1e30f;
                    if (kc + 1 > r0a) sacc[j][1] = -1e30f;
                    if (kc > r1a)     sacc[j][2] = -1e30f;
                    if (kc + 1 > r1a) sacc[j][3] = -1e30f;
                }
            }

#pragma unroll
            for (int r = 0; r < 2; r++) {
                float mt = -1e30f;
#pragma unroll
                for (int j = 0; j < 4; j++)
                    mt = fmaxf(mt, fmaxf(sacc[j][2 * r], sacc[j][2 * r + 1]));
                mt = fmaxf(mt, __shfl_xor_sync(0xffffffffu, mt, 1));
                mt = fmaxf(mt, __shfl_xor_sync(0xffffffffu, mt, 2));
                float mnew = fmaxf(m_run[r], mt);
                float corr = __expf(m_run[r] - mnew);
                m_run[r] = mnew;
                float rs = 0.0f;
#pragma unroll
                for (int j = 0; j < 4; j++) {
                    sacc[j][2 * r]     = __expf(sacc[j][2 * r] - mnew);
                    sacc[j][2 * r + 1] = __expf(sacc[j][2 * r + 1] - mnew);
                    rs += sacc[j][2 * r] + sacc[j][2 * r + 1];
                }
                rs += __shfl_xor_sync(0xffffffffu, rs, 1);
                rs += __shfl_xor_sync(0xffffffffu, rs, 2);
                l_run[r] = l_run[r] * corr + rs;
#pragma unroll
                for (int f = 0; f < 16; f++) {
                    oacc[f][2 * r]     *= corr;
                    oacc[f][2 * r + 1] *= corr;
                }
            }

#pragma unroll
            for (int t2 = 0; t2 < 2; t2++) {
                const float* s0 = sacc[2 * t2];
                const float* s1 = sacc[2 * t2 + 1];
                float lx, ly;
                ph[t2][0] = pack_hi(s0[0], s0[1], lx, ly); pl[t2][0] = pack_bf2(lx, ly);
                ph[t2][1] = pack_hi(s0[2], s0[3], lx, ly); pl[t2][1] = pack_bf2(lx, ly);
                ph[t2][2] = pack_hi(s1[0], s1[1], lx, ly); pl[t2][2] = pack_bf2(lx, ly);
                ph[t2][3] = pack_hi(s1[2], s1[3], lx, ly); pl[t2][3] = pack_bf2(lx, ly);
            }
        }

        cp_wait0();        // V ready
        __syncthreads();

        if (active) {
#pragma unroll
            for (int t2 = 0; t2 < 2; t2++) {
                uint32_t row = (uint32_t)((lane & 7) + (((lane >> 3) & 1) << 3) + 16 * t2);
#pragma unroll
                for (int g = 0; g < 8; g++) {
                    uint32_t col = (uint32_t)(16 * g + ((lane >> 4) << 3));
                    uint32_t a = sb + AVH + row * ASR + col * 2;
                    uint32_t r0, r1, r2, r3;
                    ldm_x4_t(r0, r1, r2, r3, a);
                    uint32_t vh0[2] = {r0, r1}, vh1[2] = {r2, r3};
                    ldm_x4_t(r0, r1, r2, r3, a + 8704);
                    uint32_t vl0[2] = {r0, r1}, vl1[2] = {r2, r3};
                    mma_bf16(oacc[2 * g],     ph[t2], vh0);
                    mma_bf16(oacc[2 * g],     ph[t2], vl0);
                    mma_bf16(oacc[2 * g],     pl[t2], vh0);
                    mma_bf16(oacc[2 * g + 1], ph[t2], vh1);
                    mma_bf16(oacc[2 * g + 1], ph[t2], vl1);
                    mma_bf16(oacc[2 * g + 1], pl[t2], vh1);
                }
            }
        }
    }

    // Epilogue: normalize, split, store into out-proj A buffers
    const float inv0 = 1.0f / l_run[0];
    const float inv1 = 1.0f / l_run[1];
    const size_t base0 = ((size_t)(wr + lr) * NB + n) * 2048 + colbase;
    const size_t base1 = ((size_t)(wr + lr + 8) * NB + n) * 2048 + colbase;
#pragma unroll
    for (int f = 0; f < 16; f++) {
        const int c = 8 * f + 2 * lc;
        float lx, ly;
        uint32_t h0 = pack_hi(oacc[f][0] * inv0, oacc[f][1] * inv0, lx, ly);
        uint32_t l0 = pack_bf2(lx, ly);
        *(uint32_t*)&g_Ahi[base0 + c] = h0;
        *(uint32_t*)&g_Alo[base0 + c] = l0;
        uint32_t h1 = pack_hi(oacc[f][2] * inv1, oacc[f][3] * inv1, lx, ly);
        uint32_t l1 = pack_bf2(lx, ly);
        *(uint32_t*)&g_Ahi[base1 + c] = h1;
        *(uint32_t*)&g_Alo[base1 + c] = l1;
    }
}

// ---------------------------------------------------------------------------
// kernel_launch: pure kernel launches only.
// ---------------------------------------------------------------------------
extern "C" void kernel_launch(void* const* d_in, const int* in_sizes, int n_in,
                              void* d_out, int out_size)
{
    (void)in_sizes; (void)n_in; (void)out_size;
    const float* query = (const float*)d_in[0];
    const float* qw    = (const float*)d_in[1];
    const float* qb    = (const float*)d_in[2];
    const float* kw    = (const float*)d_in[3];
    const float* kb    = (const float*)d_in[4];
    const float* vw    = (const float*)d_in[5];
    const float* vb    = (const float*)d_in[6];
    const float* ow    = (const float*)d_in[7];
    const float* ob    = (const float*)d_in[8];
    float* out = (float*)d_out;

    const float scale = 0.08838834764831845f;  // 1/sqrt(128)
    const int nA = ROWS * I_;
    dim3 gg(16, 32);

    split_query<<<nA / 1024, 256>>>(query, nA);
    split_weights<<<dim3(WELEM / 1024, 4), 256>>>(qw, kw, vw, ow);

    gemm_mma<<<gg, 256, 3 * STG2>>>(0, qb, nullptr, 0, scale);
    gemm_mma<<<gg, 256, 3 * STG2>>>(1, kb, nullptr, 1, 1.0f);
    gemm_mma<<<gg, 256, 3 * STG2>>>(2, vb, nullptr, 2, 1.0f);

    flash_attn_mma<<<dim3(L_ / 64, NB * H_), 128, ATT_SMEM>>>();

    gemm_mma<<<gg, 256, 3 * STG2>>>(3, ob, out, 3, 1.0f);
}

// round 11
// speedup vs baseline: 6.7647x; 2.3507x over previous
// v11: full fp16 single-product pipeline (P kept as split-fp16 for PV).
#include <cuda_runtime.h>
#include <cuda_fp16.h>
#include <stdint.h>
#include <math.h>

#define L_    2048
#define NB    2
#define E_    2048
#define I_    2048
#define H_    16
#define DH    128
#define ROWS  (L_*NB)        // 4096
#define WELEM (I_*E_)        // 4194304

// ---------------------------------------------------------------------------
// Scratch (device globals — no allocations allowed)
// ---------------------------------------------------------------------------
__device__ __half g_A16[(size_t)ROWS * I_];     // GEMM A input (query, then ctx)
__device__ __half g_W16[(size_t)4 * WELEM];     // weights fp16
__device__ __half g_Q16[(size_t)ROWS * I_];
__device__ __half g_K16[(size_t)ROWS * I_];
__device__ __half g_V16[(size_t)ROWS * I_];

// ---------------------------------------------------------------------------
// PTX helpers
// ---------------------------------------------------------------------------
static __device__ __forceinline__ uint32_t smem_u32(const void* p) {
    uint32_t a;
    asm("{ .reg .u64 t; cvta.to.shared.u64 t, %1; cvt.u32.u64 %0, t; }"
        : "=r"(a) : "l"(p));
    return a;
}
static __device__ __forceinline__ void cp_async16(uint32_t dst, const void* src) {
    asm volatile("cp.async.cg.shared.global [%0], [%1], 16;" :: "r"(dst), "l"(src));
}
static __device__ __forceinline__ void cp_commit() {
    asm volatile("cp.async.commit_group;");
}
static __device__ __forceinline__ void cp_wait1() {
    asm volatile("cp.async.wait_group 1;" ::: "memory");
}
static __device__ __forceinline__ void cp_wait0() {
    asm volatile("cp.async.wait_group 0;" ::: "memory");
}
static __device__ __forceinline__ void ldm_x4(uint32_t& r0, uint32_t& r1,
                                              uint32_t& r2, uint32_t& r3, uint32_t a) {
    asm volatile("ldmatrix.sync.aligned.m8n8.x4.shared.b16 {%0,%1,%2,%3}, [%4];"
                 : "=r"(r0), "=r"(r1), "=r"(r2), "=r"(r3) : "r"(a));
}
static __device__ __forceinline__ void ldm_x4_t(uint32_t& r0, uint32_t& r1,
                                                uint32_t& r2, uint32_t& r3, uint32_t a) {
    asm volatile("ldmatrix.sync.aligned.m8n8.x4.trans.shared.b16 {%0,%1,%2,%3}, [%4];"
                 : "=r"(r0), "=r"(r1), "=r"(r2), "=r"(r3) : "r"(a));
}
static __device__ __forceinline__ void mma_f16(float* d, const uint32_t* a,
                                               const uint32_t* b) {
    asm volatile(
        "mma.sync.aligned.m16n8k16.row.col.f32.f16.f16.f32 "
        "{%0,%1,%2,%3}, {%4,%5,%6,%7}, {%8,%9}, {%0,%1,%2,%3};"
        : "+f"(d[0]), "+f"(d[1]), "+f"(d[2]), "+f"(d[3])
        : "r"(a[0]), "r"(a[1]), "r"(a[2]), "r"(a[3]), "r"(b[0]), "r"(b[1]));
}
static __device__ __forceinline__ uint32_t packh(float x, float y) {
    __half2 t = __floats2half2_rn(x, y);
    return *reinterpret_cast<uint32_t*>(&t);
}
static __device__ __forceinline__ uint32_t packh_hi(float x, float y,
                                                    float& rx, float& ry) {
    __half hx = __float2half_rn(x);
    __half hy = __float2half_rn(y);
    rx = x - __half2float(hx);
    ry = y - __half2float(hy);
    __half2 t = __halves2half2(hx, hy);
    return *reinterpret_cast<uint32_t*>(&t);
}

// ---------------------------------------------------------------------------
// fp32 -> fp16 casts
// ---------------------------------------------------------------------------
__global__ __launch_bounds__(256) void cast_query(const float* __restrict__ src, int n)
{
    int i = blockIdx.x * blockDim.x + threadIdx.x;
    int stride = gridDim.x * blockDim.x;
    for (; 4 * i < n; i += stride) {
        float4 v = ((const float4*)src)[i];
        ((uint32_t*)(g_A16 + (size_t)4 * i))[0] = packh(v.x, v.y);
        ((uint32_t*)(g_A16 + (size_t)4 * i))[1] = packh(v.z, v.w);
    }
}

__global__ __launch_bounds__(256) void cast_weights(
    const float* __restrict__ qw, const float* __restrict__ kw,
    const float* __restrict__ vw, const float* __restrict__ ow)
{
    const int w = blockIdx.y;
    const float* src = (w == 0) ? qw : (w == 1) ? kw : (w == 2) ? vw : ow;
    __half* dst = g_W16 + (size_t)w * WELEM;
    int i = blockIdx.x * blockDim.x + threadIdx.x;
    int stride = gridDim.x * blockDim.x;
    for (; 4 * i < WELEM; i += stride) {
        float4 v = ((const float4*)src)[i];
        ((uint32_t*)(dst + (size_t)4 * i))[0] = packh(v.x, v.y);
        ((uint32_t*)(dst + (size_t)4 * i))[1] = packh(v.z, v.w);
    }
}

// ---------------------------------------------------------------------------
// fp16 single-product GEMM: C[4096,2048] = alpha*(A @ B^T + bias)
// Tile 128x128, BK=32, 3-stage single-barrier pipeline.
// Stage = A[128x32] + B[128x32] fp16, XOR-swizzled (chunk ^= (row>>1)&3):
// 16 KB/stage, 3 stages = 49152 B exactly (no opt-in attribute).
// out_tag 0/1/2 -> fp16 to g_Q16/g_K16/g_V16; 3 -> fp32 to Copt.
// ---------------------------------------------------------------------------
#define GTIL 8192            // bytes per sub-tile (128 rows x 64B)
#define GSTG 16384           // bytes per stage

__global__ __launch_bounds__(256) void gemm_f16(
    int w_idx, const float* __restrict__ bias,
    float* __restrict__ Copt, int out_tag, float alpha)
{
    extern __shared__ __align__(16) char smem[];
    const uint32_t sbase = smem_u32(smem);

    const int tid  = threadIdx.x;
    const int wid  = tid >> 5;
    const int lane = tid & 31;
    const int wm = wid >> 2;
    const int wn = wid & 3;
    const int bm = blockIdx.y * 128;
    const int bn = blockIdx.x * 128;

    const __half* Bw = g_W16 + (size_t)w_idx * WELEM;

    // Loader: 1024 chunks/stage (A 512 + B 512), 4 per thread.
    uint32_t ldst[4]; const __half* lsrc[4];
#pragma unroll
    for (int t = 0; t < 4; t++) {
        int idx = tid + t * 256;
        int tile = idx >> 9;
        int row  = (idx & 511) >> 2;
        int c    = idx & 3;
        int swc  = c ^ ((row >> 1) & 3);
        ldst[t] = (uint32_t)(tile * GTIL + row * 64 + swc * 16);
        lsrc[t] = (tile ? (Bw + (size_t)(bn + row) * 2048)
                        : (g_A16 + (size_t)(bm + row) * 2048)) + c * 8;
    }

    const int frow = lane & 15;
    const int fhal = lane >> 4;
    const int fsw  = (frow >> 1) & 3;
    const uint32_t cof0 = (uint32_t)(((0 + fhal) ^ fsw) * 16);  // ks=0
    const uint32_t cof1 = (uint32_t)(((2 + fhal) ^ fsw) * 16);  // ks=1

    float acc[4][4][4];
#pragma unroll
    for (int i = 0; i < 4; i++)
#pragma unroll
        for (int j = 0; j < 4; j++)
#pragma unroll
            for (int q = 0; q < 4; q++) acc[i][j][q] = 0.0f;

    // Prologue: stages 0, 1
#pragma unroll
    for (int ps = 0; ps < 2; ps++) {
        const uint32_t stg = sbase + (uint32_t)(ps * GSTG);
#pragma unroll
        for (int t = 0; t < 4; t++)
            cp_async16(stg + ldst[t], lsrc[t] + ps * 32);
        cp_commit();
    }

    int cur = 0;
    for (int s = 0; s < 64; s++) {
        if (s < 63) cp_wait1(); else cp_wait0();
        __syncthreads();

        if (s + 2 < 64) {
            int nxt2 = cur + 2; if (nxt2 >= 3) nxt2 -= 3;
            const uint32_t stg = sbase + (uint32_t)(nxt2 * GSTG);
#pragma unroll
            for (int t = 0; t < 4; t++)
                cp_async16(stg + ldst[t], lsrc[t] + (s + 2) * 32);
            cp_commit();
        }

        const uint32_t stg = sbase + (uint32_t)(cur * GSTG);
        cur++; if (cur == 3) cur = 0;

#pragma unroll
        for (int ks = 0; ks < 2; ks++) {
            const uint32_t cof = ks ? cof1 : cof0;
            uint32_t bf[4][2];
#pragma unroll
            for (int pair = 0; pair < 2; pair++) {
                uint32_t r0, r1, r2, r3;
                ldm_x4(r0, r1, r2, r3,
                       stg + GTIL + (uint32_t)((wn * 32 + pair * 16 + frow) * 64) + cof);
                bf[2 * pair][0] = r0; bf[2 * pair][1] = r2;
                bf[2 * pair + 1][0] = r1; bf[2 * pair + 1][1] = r3;
            }
#pragma unroll
            for (int mf = 0; mf < 4; mf++) {
                uint32_t af[4];
                ldm_x4(af[0], af[1], af[2], af[3],
                       stg + (uint32_t)((wm * 64 + mf * 16 + frow) * 64) + cof);
#pragma unroll
                for (int nf = 0; nf < 4; nf++)
                    mma_f16(acc[mf][nf], af, bf[nf]);
            }
        }
    }

    // Epilogue
    if (out_tag == 3) {
#pragma unroll
        for (int mf = 0; mf < 4; mf++) {
#pragma unroll
            for (int nf = 0; nf < 4; nf++) {
                const int row0 = bm + wm * 64 + mf * 16 + (lane >> 2);
                const int col  = bn + wn * 32 + nf * 8 + (lane & 3) * 2;
                float2 bv = *(const float2*)&bias[col];
                float2 o0, o1;
                o0.x = alpha * (acc[mf][nf][0] + bv.x);
                o0.y = alpha * (acc[mf][nf][1] + bv.y);
                o1.x = alpha * (acc[mf][nf][2] + bv.x);
                o1.y = alpha * (acc[mf][nf][3] + bv.y);
                *(float2*)&Copt[(size_t)row0 * 2048 + col] = o0;
                *(float2*)&Copt[(size_t)(row0 + 8) * 2048 + col] = o1;
            }
        }
    } else {
        __half* dst = (out_tag == 0) ? g_Q16 : (out_tag == 1) ? g_K16 : g_V16;
#pragma unroll
        for (int mf = 0; mf < 4; mf++) {
#pragma unroll
            for (int nf = 0; nf < 4; nf++) {
                const int row0 = bm + wm * 64 + mf * 16 + (lane >> 2);
                const int col  = bn + wn * 32 + nf * 8 + (lane & 3) * 2;
                float2 bv = *(const float2*)&bias[col];
                *(uint32_t*)&dst[(size_t)row0 * 2048 + col] =
                    packh(alpha * (acc[mf][nf][0] + bv.x),
                          alpha * (acc[mf][nf][1] + bv.y));
                *(uint32_t*)&dst[(size_t)(row0 + 8) * 2048 + col] =
                    packh(alpha * (acc[mf][nf][2] + bv.x),
                          alpha * (acc[mf][nf][3] + bv.y));
            }
        }
    }
}

// ---------------------------------------------------------------------------
// fp16 HMMA causal flash attention, 128 threads (4 warps).
// Single-product QK^T; P as split-fp16 (2-MMA PV). K/V separate commit
// groups so QK^T overlaps the V load.
// ---------------------------------------------------------------------------
#define ASR 272                     // smem row stride bytes (136 halves)
#define AV16 8704
#define ATT_SMEM 17408

__global__ __launch_bounds__(128, 1) void flash_attn_f16()
{
    extern __shared__ __align__(16) char smem[];
    const uint32_t sb = smem_u32(smem);
    const int tid  = threadIdx.x;
    const int wid  = tid >> 5;
    const int lane = tid & 31;
    const int qt = blockIdx.x;
    const int bb = blockIdx.y;
    const int n  = bb / H_;
    const int h  = bb % H_;
    const int q0 = qt * 64;
    const int wr = q0 + wid * 16;
    const int colbase = h * DH;
    const int lr = lane >> 2;
    const int lc = lane & 3;

    // Q fragments direct from gmem (A layout m16k16)
    uint32_t qf[8][4];
    {
        const size_t base0 = ((size_t)(wr + lr) * NB + n) * 2048 + colbase;
        const size_t base1 = ((size_t)(wr + lr + 8) * NB + n) * 2048 + colbase;
#pragma unroll
        for (int t = 0; t < 8; t++) {
            const int k = 16 * t + 2 * lc;
            qf[t][0] = *(const uint32_t*)&g_Q16[base0 + k];
            qf[t][1] = *(const uint32_t*)&g_Q16[base1 + k];
            qf[t][2] = *(const uint32_t*)&g_Q16[base0 + k + 8];
            qf[t][3] = *(const uint32_t*)&g_Q16[base1 + k + 8];
        }
    }

    float oacc[16][4];
#pragma unroll
    for (int f = 0; f < 16; f++)
#pragma unroll
        for (int q = 0; q < 4; q++) oacc[f][q] = 0.0f;
    float m_run[2] = {-1e30f, -1e30f};
    float l_run[2] = {0.0f, 0.0f};

    const int jt_max = 2 * qt + 1;
    for (int jt = 0; jt <= jt_max; jt++) {
        const int k0 = jt * 32;
        __syncthreads();   // prior tile's smem readers done

        // Group 1: K tile (512 chunks, 4/thread)
#pragma unroll
        for (int i = 0; i < 4; i++) {
            int c = tid + i * 128;
            int row = c >> 4;
            int seg = c & 15;
            cp_async16(sb + row * ASR + seg * 16,
                       g_K16 + ((size_t)(k0 + row) * NB + n) * 2048 + colbase + seg * 8);
        }
        cp_commit();
        // Group 2: V tile
#pragma unroll
        for (int i = 0; i < 4; i++) {
            int c = tid + i * 128;
            int row = c >> 4;
            int seg = c & 15;
            cp_async16(sb + AV16 + row * ASR + seg * 16,
                       g_V16 + ((size_t)(k0 + row) * NB + n) * 2048 + colbase + seg * 8);
        }
        cp_commit();

        cp_wait1();        // K ready
        __syncthreads();

        const bool active = (k0 <= wr + 15);
        uint32_t ph[2][4], pl[2][4];

        if (active) {
            float sacc[4][4];
#pragma unroll
            for (int j = 0; j < 4; j++)
#pragma unroll
                for (int q = 0; q < 4; q++) sacc[j][q] = 0.0f;

#pragma unroll
            for (int t = 0; t < 8; t++) {
                uint32_t kf[4][2];
#pragma unroll
                for (int g = 0; g < 2; g++) {
                    uint32_t row = (uint32_t)((lane & 7) + ((lane >> 4) << 3) + 16 * g);
                    uint32_t a = sb + row * ASR + 32 * t + (((lane >> 3) & 1) << 4);
                    uint32_t r0, r1, r2, r3;
                    ldm_x4(r0, r1, r2, r3, a);
                    kf[2 * g][0] = r0; kf[2 * g][1] = r1;
                    kf[2 * g + 1][0] = r2; kf[2 * g + 1][1] = r3;
                }
#pragma unroll
                for (int j = 0; j < 4; j++)
                    mma_f16(sacc[j], qf[t], kf[j]);
            }

            if (k0 + 31 > wr) {
                const int r0a = wr + lr, r1a = r0a + 8;
#pragma unroll
                for (int j = 0; j < 4; j++) {
                    int kc = k0 + 8 * j + 2 * lc;
                    if (kc > r0a)     sacc[j][0] = -1e30f;
                    if (kc + 1 > r0a) sacc[j][1] = -1e30f;
                    if (kc > r1a)     sacc[j][2] = -1e30f;
                    if (kc + 1 > r1a) sacc[j][3] = -1e30f;
                }
            }

#pragma unroll
            for (int r = 0; r < 2; r++) {
                float mt = -1e30f;
#pragma unroll
                for (int j = 0; j < 4; j++)
                    mt = fmaxf(mt, fmaxf(sacc[j][2 * r], sacc[j][2 * r + 1]));
                mt = fmaxf(mt, __shfl_xor_sync(0xffffffffu, mt, 1));
                mt = fmaxf(mt, __shfl_xor_sync(0xffffffffu, mt, 2));
                float mnew = fmaxf(m_run[r], mt);
                float corr = __expf(m_run[r] - mnew);
                m_run[r] = mnew;
                float rs = 0.0f;
#pragma unroll
                for (int j = 0; j < 4; j++) {
                    sacc[j][2 * r]     = __expf(sacc[j][2 * r] - mnew);
                    sacc[j][2 * r + 1] = __expf(sacc[j][2 * r + 1] - mnew);
                    rs += sacc[j][2 * r] + sacc[j][2 * r + 1];
                }
                rs += __shfl_xor_sync(0xffffffffu, rs, 1);
                rs += __shfl_xor_sync(0xffffffffu, rs, 2);
                l_run[r] = l_run[r] * corr + rs;
#pragma unroll
                for (int f = 0; f < 16; f++) {
                    oacc[f][2 * r]     *= corr;
                    oacc[f][2 * r + 1] *= corr;
                }
            }

            // P fragments: split fp16 hi/lo, A-operand layout
#pragma unroll
            for (int t2 = 0; t2 < 2; t2++) {
                const float* s0 = sacc[2 * t2];
                const float* s1 = sacc[2 * t2 + 1];
                float lx, ly;
                ph[t2][0] = packh_hi(s0[0], s0[1], lx, ly); pl[t2][0] = packh(lx, ly);
                ph[t2][1] = packh_hi(s0[2], s0[3], lx, ly); pl[t2][1] = packh(lx, ly);
                ph[t2][2] = packh_hi(s1[0], s1[1], lx, ly); pl[t2][2] = packh(lx, ly);
                ph[t2][3] = packh_hi(s1[2], s1[3], lx, ly); pl[t2][3] = packh(lx, ly);
            }
        }

        cp_wait0();        // V ready
        __syncthreads();

        if (active) {
#pragma unroll
            for (int t2 = 0; t2 < 2; t2++) {
                uint32_t row = (uint32_t)((lane & 7) + (((lane >> 3) & 1) << 3) + 16 * t2);
#pragma unroll
                for (int g = 0; g < 8; g++) {
                    uint32_t col = (uint32_t)(16 * g + ((lane >> 4) << 3));
                    uint32_t a = sb + AV16 + row * ASR + col * 2;
                    uint32_t r0, r1, r2, r3;
                    ldm_x4_t(r0, r1, r2, r3, a);
                    uint32_t v0[2] = {r0, r1}, v1[2] = {r2, r3};
                    mma_f16(oacc[2 * g],     ph[t2], v0);
                    mma_f16(oacc[2 * g],     pl[t2], v0);
                    mma_f16(oacc[2 * g + 1], ph[t2], v1);
                    mma_f16(oacc[2 * g + 1], pl[t2], v1);
                }
            }
        }
    }

    // Epilogue: normalize, cast fp16, store into out-proj A buffer
    const float inv0 = 1.0f / l_run[0];
    const float inv1 = 1.0f / l_run[1];
    const size_t base0 = ((size_t)(wr + lr) * NB + n) * 2048 + colbase;
    const size_t base1 = ((size_t)(wr + lr + 8) * NB + n) * 2048 + colbase;
#pragma unroll
    for (int f = 0; f < 16; f++) {
        const int c = 8 * f + 2 * lc;
        *(uint32_t*)&g_A16[base0 + c] = packh(oacc[f][0] * inv0, oacc[f][1] * inv0);
        *(uint32_t*)&g_A16[base1 + c] = packh(oacc[f][2] * inv1, oacc[f][3] * inv1);
    }
}

// ---------------------------------------------------------------------------
// kernel_launch: pure kernel launches only.
// ---------------------------------------------------------------------------
extern "C" void kernel_launch(void* const* d_in, const int* in_sizes, int n_in,
                              void* d_out, int out_size)
{
    (void)in_sizes; (void)n_in; (void)out_size;
    const float* query = (const float*)d_in[0];
    const float* qw    = (const float*)d_in[1];
    const float* qb    = (const float*)d_in[2];
    const float* kw    = (const float*)d_in[3];
    const float* kb    = (const float*)d_in[4];
    const float* vw    = (const float*)d_in[5];
    const float* vb    = (const float*)d_in[6];
    const float* ow    = (const float*)d_in[7];
    const float* ob    = (const float*)d_in[8];
    float* out = (float*)d_out;

    const float scale = 0.08838834764831845f;  // 1/sqrt(128)
    const int nA = ROWS * I_;
    dim3 gg(16, 32);

    cast_query<<<nA / 1024, 256>>>(query, nA);
    cast_weights<<<dim3(WELEM / 1024, 4), 256>>>(qw, kw, vw, ow);

    gemm_f16<<<gg, 256, 3 * GSTG>>>(0, qb, nullptr, 0, scale);
    gemm_f16<<<gg, 256, 3 * GSTG>>>(1, kb, nullptr, 1, 1.0f);
    gemm_f16<<<gg, 256, 3 * GSTG>>>(2, vb, nullptr, 2, 1.0f);

    flash_attn_f16<<<dim3(L_ / 64, NB * H_), 128, ATT_SMEM>>>();

    gemm_f16<<<gg, 256, 3 * GSTG>>>(3, ob, out, 3, 1.0f);
}

// round 12
// speedup vs baseline: 7.5848x; 1.1212x over previous
// v12: QKV projections fused into one launch (wave balance); attention PV
//      single-product fp16 (P-split dropped).
#include <cuda_runtime.h>
#include <cuda_fp16.h>
#include <stdint.h>
#include <math.h>

#define L_    2048
#define NB    2
#define E_    2048
#define I_    2048
#define H_    16
#define DH    128
#define ROWS  (L_*NB)        // 4096
#define WELEM (I_*E_)        // 4194304

__device__ __half g_A16[(size_t)ROWS * I_];     // GEMM A input (query, then ctx)
__device__ __half g_W16[(size_t)4 * WELEM];     // weights fp16
__device__ __half g_Q16[(size_t)ROWS * I_];
__device__ __half g_K16[(size_t)ROWS * I_];
__device__ __half g_V16[(size_t)ROWS * I_];

// ---------------------------------------------------------------------------
static __device__ __forceinline__ uint32_t smem_u32(const void* p) {
    uint32_t a;
    asm("{ .reg .u64 t; cvta.to.shared.u64 t, %1; cvt.u32.u64 %0, t; }"
        : "=r"(a) : "l"(p));
    return a;
}
static __device__ __forceinline__ void cp_async16(uint32_t dst, const void* src) {
    asm volatile("cp.async.cg.shared.global [%0], [%1], 16;" :: "r"(dst), "l"(src));
}
static __device__ __forceinline__ void cp_commit() {
    asm volatile("cp.async.commit_group;");
}
static __device__ __forceinline__ void cp_wait1() {
    asm volatile("cp.async.wait_group 1;" ::: "memory");
}
static __device__ __forceinline__ void cp_wait0() {
    asm volatile("cp.async.wait_group 0;" ::: "memory");
}
static __device__ __forceinline__ void ldm_x4(uint32_t& r0, uint32_t& r1,
                                              uint32_t& r2, uint32_t& r3, uint32_t a) {
    asm volatile("ldmatrix.sync.aligned.m8n8.x4.shared.b16 {%0,%1,%2,%3}, [%4];"
                 : "=r"(r0), "=r"(r1), "=r"(r2), "=r"(r3) : "r"(a));
}
static __device__ __forceinline__ void ldm_x4_t(uint32_t& r0, uint32_t& r1,
                                                uint32_t& r2, uint32_t& r3, uint32_t a) {
    asm volatile("ldmatrix.sync.aligned.m8n8.x4.trans.shared.b16 {%0,%1,%2,%3}, [%4];"
                 : "=r"(r0), "=r"(r1), "=r"(r2), "=r"(r3) : "r"(a));
}
static __device__ __forceinline__ void mma_f16(float* d, const uint32_t* a,
                                               const uint32_t* b) {
    asm volatile(
        "mma.sync.aligned.m16n8k16.row.col.f32.f16.f16.f32 "
        "{%0,%1,%2,%3}, {%4,%5,%6,%7}, {%8,%9}, {%0,%1,%2,%3};"
        : "+f"(d[0]), "+f"(d[1]), "+f"(d[2]), "+f"(d[3])
        : "r"(a[0]), "r"(a[1]), "r"(a[2]), "r"(a[3]), "r"(b[0]), "r"(b[1]));
}
static __device__ __forceinline__ uint32_t packh(float x, float y) {
    __half2 t = __floats2half2_rn(x, y);
    return *reinterpret_cast<uint32_t*>(&t);
}

// ---------------------------------------------------------------------------
// fp32 -> fp16 casts
// ---------------------------------------------------------------------------
__global__ __launch_bounds__(256) void cast_query(const float* __restrict__ src, int n)
{
    int i = blockIdx.x * blockDim.x + threadIdx.x;
    int stride = gridDim.x * blockDim.x;
    for (; 4 * i < n; i += stride) {
        float4 v = ((const float4*)src)[i];
        ((uint32_t*)(g_A16 + (size_t)4 * i))[0] = packh(v.x, v.y);
        ((uint32_t*)(g_A16 + (size_t)4 * i))[1] = packh(v.z, v.w);
    }
}

__global__ __launch_bounds__(256) void cast_weights(
    const float* __restrict__ qw, const float* __restrict__ kw,
    const float* __restrict__ vw, const float* __restrict__ ow)
{
    const int w = blockIdx.y;
    const float* src = (w == 0) ? qw : (w == 1) ? kw : (w == 2) ? vw : ow;
    __half* dst = g_W16 + (size_t)w * WELEM;
    int i = blockIdx.x * blockDim.x + threadIdx.x;
    int stride = gridDim.x * blockDim.x;
    for (; 4 * i < WELEM; i += stride) {
        float4 v = ((const float4*)src)[i];
        ((uint32_t*)(dst + (size_t)4 * i))[0] = packh(v.x, v.y);
        ((uint32_t*)(dst + (size_t)4 * i))[1] = packh(v.z, v.w);
    }
}

// ---------------------------------------------------------------------------
// fp16 GEMM core: tile 128x128, BK=32, 3-stage single-barrier pipeline.
// QKV=true: w/bias/dst/alpha selected by blockIdx.z, fp16 output.
// QKV=false: w_idx=3 (out-proj), fp32 output to Copt.
// ---------------------------------------------------------------------------
#define GTIL 8192            // bytes per sub-tile (128 rows x 64B)
#define GSTG 16384           // bytes per stage

template<bool QKV>
__global__ __launch_bounds__(256) void gemm_f16(
    const float* __restrict__ b0, const float* __restrict__ b1,
    const float* __restrict__ b2, float* __restrict__ Copt, float scale)
{
    extern __shared__ __align__(16) char smem[];
    const uint32_t sbase = smem_u32(smem);

    const int tid  = threadIdx.x;
    const int wid  = tid >> 5;
    const int lane = tid & 31;
    const int wm = wid >> 2;
    const int wn = wid & 3;
    const int bm = blockIdx.y * 128;
    const int bn = blockIdx.x * 128;
    const int z  = QKV ? blockIdx.z : 3;

    const __half* Bw = g_W16 + (size_t)z * WELEM;
    const float* bias = QKV ? (z == 0 ? b0 : (z == 1 ? b1 : b2)) : b0;
    const float alpha = (QKV && z == 0) ? scale : 1.0f;

    uint32_t ldst[4]; const __half* lsrc[4];
#pragma unroll
    for (int t = 0; t < 4; t++) {
        int idx = tid + t * 256;
        int tile = idx >> 9;
        int row  = (idx & 511) >> 2;
        int c    = idx & 3;
        int swc  = c ^ ((row >> 1) & 3);
        ldst[t] = (uint32_t)(tile * GTIL + row * 64 + swc * 16);
        lsrc[t] = (tile ? (Bw + (size_t)(bn + row) * 2048)
                        : (g_A16 + (size_t)(bm + row) * 2048)) + c * 8;
    }

    const int frow = lane & 15;
    const int fhal = lane >> 4;
    const int fsw  = (frow >> 1) & 3;
    const uint32_t cof0 = (uint32_t)(((0 + fhal) ^ fsw) * 16);
    const uint32_t cof1 = (uint32_t)(((2 + fhal) ^ fsw) * 16);

    float acc[4][4][4];
#pragma unroll
    for (int i = 0; i < 4; i++)
#pragma unroll
        for (int j = 0; j < 4; j++)
#pragma unroll
            for (int q = 0; q < 4; q++) acc[i][j][q] = 0.0f;

#pragma unroll
    for (int ps = 0; ps < 2; ps++) {
        const uint32_t stg = sbase + (uint32_t)(ps * GSTG);
#pragma unroll
        for (int t = 0; t < 4; t++)
            cp_async16(stg + ldst[t], lsrc[t] + ps * 32);
        cp_commit();
    }

    int cur = 0;
    for (int s = 0; s < 64; s++) {
        if (s < 63) cp_wait1(); else cp_wait0();
        __syncthreads();

        if (s + 2 < 64) {
            int nxt2 = cur + 2; if (nxt2 >= 3) nxt2 -= 3;
            const uint32_t stg = sbase + (uint32_t)(nxt2 * GSTG);
#pragma unroll
            for (int t = 0; t < 4; t++)
                cp_async16(stg + ldst[t], lsrc[t] + (s + 2) * 32);
            cp_commit();
        }

        const uint32_t stg = sbase + (uint32_t)(cur * GSTG);
        cur++; if (cur == 3) cur = 0;

#pragma unroll
        for (int ks = 0; ks < 2; ks++) {
            const uint32_t cof = ks ? cof1 : cof0;
            uint32_t bf[4][2];
#pragma unroll
            for (int pair = 0; pair < 2; pair++) {
                uint32_t r0, r1, r2, r3;
                ldm_x4(r0, r1, r2, r3,
                       stg + GTIL + (uint32_t)((wn * 32 + pair * 16 + frow) * 64) + cof);
                bf[2 * pair][0] = r0; bf[2 * pair][1] = r2;
                bf[2 * pair + 1][0] = r1; bf[2 * pair + 1][1] = r3;
            }
#pragma unroll
            for (int mf = 0; mf < 4; mf++) {
                uint32_t af[4];
                ldm_x4(af[0], af[1], af[2], af[3],
                       stg + (uint32_t)((wm * 64 + mf * 16 + frow) * 64) + cof);
#pragma unroll
                for (int nf = 0; nf < 4; nf++)
                    mma_f16(acc[mf][nf], af, bf[nf]);
            }
        }
    }

    if (!QKV) {
#pragma unroll
        for (int mf = 0; mf < 4; mf++) {
#pragma unroll
            for (int nf = 0; nf < 4; nf++) {
                const int row0 = bm + wm * 64 + mf * 16 + (lane >> 2);
                const int col  = bn + wn * 32 + nf * 8 + (lane & 3) * 2;
                float2 bv = *(const float2*)&bias[col];
                float2 o0, o1;
                o0.x = acc[mf][nf][0] + bv.x;
                o0.y = acc[mf][nf][1] + bv.y;
                o1.x = acc[mf][nf][2] + bv.x;
                o1.y = acc[mf][nf][3] + bv.y;
                *(float2*)&Copt[(size_t)row0 * 2048 + col] = o0;
                *(float2*)&Copt[(size_t)(row0 + 8) * 2048 + col] = o1;
            }
        }
    } else {
        __half* dst = (z == 0) ? g_Q16 : (z == 1) ? g_K16 : g_V16;
#pragma unroll
        for (int mf = 0; mf < 4; mf++) {
#pragma unroll
            for (int nf = 0; nf < 4; nf++) {
                const int row0 = bm + wm * 64 + mf * 16 + (lane >> 2);
                const int col  = bn + wn * 32 + nf * 8 + (lane & 3) * 2;
                float2 bv = *(const float2*)&bias[col];
                *(uint32_t*)&dst[(size_t)row0 * 2048 + col] =
                    packh(alpha * (acc[mf][nf][0] + bv.x),
                          alpha * (acc[mf][nf][1] + bv.y));
                *(uint32_t*)&dst[(size_t)(row0 + 8) * 2048 + col] =
                    packh(alpha * (acc[mf][nf][2] + bv.x),
                          alpha * (acc[mf][nf][3] + bv.y));
            }
        }
    }
}

// ---------------------------------------------------------------------------
// fp16 HMMA causal flash attention, 128 threads (4 warps).
// Single-product QK^T and PV (P cast once to fp16). K/V separate commit
// groups so QK^T overlaps the V load.
// ---------------------------------------------------------------------------
#define ASR 272                     // smem row stride bytes (136 halves)
#define AV16 8704
#define ATT_SMEM 17408

__global__ __launch_bounds__(128, 1) void flash_attn_f16()
{
    extern __shared__ __align__(16) char smem[];
    const uint32_t sb = smem_u32(smem);
    const int tid  = threadIdx.x;
    const int wid  = tid >> 5;
    const int lane = tid & 31;
    const int qt = blockIdx.x;
    const int bb = blockIdx.y;
    const int n  = bb / H_;
    const int h  = bb % H_;
    const int q0 = qt * 64;
    const int wr = q0 + wid * 16;
    const int colbase = h * DH;
    const int lr = lane >> 2;
    const int lc = lane & 3;

    uint32_t qf[8][4];
    {
        const size_t base0 = ((size_t)(wr + lr) * NB + n) * 2048 + colbase;
        const size_t base1 = ((size_t)(wr + lr + 8) * NB + n) * 2048 + colbase;
#pragma unroll
        for (int t = 0; t < 8; t++) {
            const int k = 16 * t + 2 * lc;
            qf[t][0] = *(const uint32_t*)&g_Q16[base0 + k];
            qf[t][1] = *(const uint32_t*)&g_Q16[base1 + k];
            qf[t][2] = *(const uint32_t*)&g_Q16[base0 + k + 8];
            qf[t][3] = *(const uint32_t*)&g_Q16[base1 + k + 8];
        }
    }

    float oacc[16][4];
#pragma unroll
    for (int f = 0; f < 16; f++)
#pragma unroll
        for (int q = 0; q < 4; q++) oacc[f][q] = 0.0f;
    float m_run[2] = {-1e30f, -1e30f};
    float l_run[2] = {0.0f, 0.0f};

    const int jt_max = 2 * qt + 1;
    for (int jt = 0; jt <= jt_max; jt++) {
        const int k0 = jt * 32;
        __syncthreads();

#pragma unroll
        for (int i = 0; i < 4; i++) {
            int c = tid + i * 128;
            int row = c >> 4;
            int seg = c & 15;
            cp_async16(sb + row * ASR + seg * 16,
                       g_K16 + ((size_t)(k0 + row) * NB + n) * 2048 + colbase + seg * 8);
        }
        cp_commit();
#pragma unroll
        for (int i = 0; i < 4; i++) {
            int c = tid + i * 128;
            int row = c >> 4;
            int seg = c & 15;
            cp_async16(sb + AV16 + row * ASR + seg * 16,
                       g_V16 + ((size_t)(k0 + row) * NB + n) * 2048 + colbase + seg * 8);
        }
        cp_commit();

        cp_wait1();        // K ready
        __syncthreads();

        const bool active = (k0 <= wr + 15);
        uint32_t ph[2][4];

        if (active) {
            float sacc[4][4];
#pragma unroll
            for (int j = 0; j < 4; j++)
#pragma unroll
                for (int q = 0; q < 4; q++) sacc[j][q] = 0.0f;

#pragma unroll
            for (int t = 0; t < 8; t++) {
                uint32_t kf[4][2];
#pragma unroll
                for (int g = 0; g < 2; g++) {
                    uint32_t row = (uint32_t)((lane & 7) + ((lane >> 4) << 3) + 16 * g);
                    uint32_t a = sb + row * ASR + 32 * t + (((lane >> 3) & 1) << 4);
                    uint32_t r0, r1, r2, r3;
                    ldm_x4(r0, r1, r2, r3, a);
                    kf[2 * g][0] = r0; kf[2 * g][1] = r1;
                    kf[2 * g + 1][0] = r2; kf[2 * g + 1][1] = r3;
                }
#pragma unroll
                for (int j = 0; j < 4; j++)
                    mma_f16(sacc[j], qf[t], kf[j]);
            }

            if (k0 + 31 > wr) {
                const int r0a = wr + lr, r1a = r0a + 8;
#pragma unroll
                for (int j = 0; j < 4; j++) {
                    int kc = k0 + 8 * j + 2 * lc;
                    if (kc > r0a)     sacc[j][0] = -1e30f;
                    if (kc + 1 > r0a) sacc[j][1] = -1e30f;
                    if (kc > r1a)     sacc[j][2] = -1e30f;
                    if (kc + 1 > r1a) sacc[j][3] = -1e30f;
                }
            }

#pragma unroll
            for (int r = 0; r < 2; r++) {
                float mt = -1e30f;
#pragma unroll
                for (int j = 0; j < 4; j++)
                    mt = fmaxf(mt, fmaxf(sacc[j][2 * r], sacc[j][2 * r + 1]));
                mt = fmaxf(mt, __shfl_xor_sync(0xffffffffu, mt, 1));
                mt = fmaxf(mt, __shfl_xor_sync(0xffffffffu, mt, 2));
                float mnew = fmaxf(m_run[r], mt);
                float corr = __expf(m_run[r] - mnew);
                m_run[r] = mnew;
                float rs = 0.0f;
#pragma unroll
                for (int j = 0; j < 4; j++) {
                    sacc[j][2 * r]     = __expf(sacc[j][2 * r] - mnew);
                    sacc[j][2 * r + 1] = __expf(sacc[j][2 * r + 1] - mnew);
                    rs += sacc[j][2 * r] + sacc[j][2 * r + 1];
                }
                rs += __shfl_xor_sync(0xffffffffu, rs, 1);
                rs += __shfl_xor_sync(0xffffffffu, rs, 2);
                l_run[r] = l_run[r] * corr + rs;
#pragma unroll
                for (int f = 0; f < 16; f++) {
                    oacc[f][2 * r]     *= corr;
                    oacc[f][2 * r + 1] *= corr;
                }
            }

#pragma unroll
            for (int t2 = 0; t2 < 2; t2++) {
                const float* s0 = sacc[2 * t2];
                const float* s1 = sacc[2 * t2 + 1];
                ph[t2][0] = packh(s0[0], s0[1]);
                ph[t2][1] = packh(s0[2], s0[3]);
                ph[t2][2] = packh(s1[0], s1[1]);
                ph[t2][3] = packh(s1[2], s1[3]);
            }
        }

        cp_wait0();        // V ready
        __syncthreads();

        if (active) {
#pragma unroll
            for (int t2 = 0; t2 < 2; t2++) {
                uint32_t row = (uint32_t)((lane & 7) + (((lane >> 3) & 1) << 3) + 16 * t2);
#pragma unroll
                for (int g = 0; g < 8; g++) {
                    uint32_t col = (uint32_t)(16 * g + ((lane >> 4) << 3));
                    uint32_t a = sb + AV16 + row * ASR + col * 2;
                    uint32_t r0, r1, r2, r3;
                    ldm_x4_t(r0, r1, r2, r3, a);
                    uint32_t v0[2] = {r0, r1}, v1[2] = {r2, r3};
                    mma_f16(oacc[2 * g],     ph[t2], v0);
                    mma_f16(oacc[2 * g + 1], ph[t2], v1);
                }
            }
        }
    }

    const float inv0 = 1.0f / l_run[0];
    const float inv1 = 1.0f / l_run[1];
    const size_t base0 = ((size_t)(wr + lr) * NB + n) * 2048 + colbase;
    const size_t base1 = ((size_t)(wr + lr + 8) * NB + n) * 2048 + colbase;
#pragma unroll
    for (int f = 0; f < 16; f++) {
        const int c = 8 * f + 2 * lc;
        *(uint32_t*)&g_A16[base0 + c] = packh(oacc[f][0] * inv0, oacc[f][1] * inv0);
        *(uint32_t*)&g_A16[base1 + c] = packh(oacc[f][2] * inv1, oacc[f][3] * inv1);
    }
}

// ---------------------------------------------------------------------------
extern "C" void kernel_launch(void* const* d_in, const int* in_sizes, int n_in,
                              void* d_out, int out_size)
{
    (void)in_sizes; (void)n_in; (void)out_size;
    const float* query = (const float*)d_in[0];
    const float* qw    = (const float*)d_in[1];
    const float* qb    = (const float*)d_in[2];
    const float* kw    = (const float*)d_in[3];
    const float* kb    = (const float*)d_in[4];
    const float* vw    = (const float*)d_in[5];
    const float* vb    = (const float*)d_in[6];
    const float* ow    = (const float*)d_in[7];
    const float* ob    = (const float*)d_in[8];
    float* out = (float*)d_out;

    const float scale = 0.08838834764831845f;  // 1/sqrt(128)
    const int nA = ROWS * I_;

    cast_query<<<nA / 1024, 256>>>(query, nA);
    cast_weights<<<dim3(WELEM / 1024, 4), 256>>>(qw, kw, vw, ow);

    // Q, K, V projections fused: z = 0/1/2
    gemm_f16<true><<<dim3(16, 32, 3), 256, 3 * GSTG>>>(qb, kb, vb, nullptr, scale);

    flash_attn_f16<<<dim3(L_ / 64, NB * H_), 128, ATT_SMEM>>>();

    // Output projection (fp32 out)
    gemm_f16<false><<<dim3(16, 32, 1), 256, 3 * GSTG>>>(ob, nullptr, nullptr, out, 1.0f);
}

// round 13
// speedup vs baseline: 7.7381x; 1.0202x over previous
// v13: attention occupancy (Q->smem, 3 CTAs/SM) + heavy-first causal order.
#include <cuda_runtime.h>
#include <cuda_fp16.h>
#include <stdint.h>
#include <math.h>

#define L_    2048
#define NB    2
#define E_    2048
#define I_    2048
#define H_    16
#define DH    128
#define ROWS  (L_*NB)        // 4096
#define WELEM (I_*E_)        // 4194304

__device__ __half g_A16[(size_t)ROWS * I_];     // GEMM A input (query, then ctx)
__device__ __half g_W16[(size_t)4 * WELEM];     // weights fp16
__device__ __half g_Q16[(size_t)ROWS * I_];
__device__ __half g_K16[(size_t)ROWS * I_];
__device__ __half g_V16[(size_t)ROWS * I_];

// ---------------------------------------------------------------------------
static __device__ __forceinline__ uint32_t smem_u32(const void* p) {
    uint32_t a;
    asm("{ .reg .u64 t; cvta.to.shared.u64 t, %1; cvt.u32.u64 %0, t; }"
        : "=r"(a) : "l"(p));
    return a;
}
static __device__ __forceinline__ void cp_async16(uint32_t dst, const void* src) {
    asm volatile("cp.async.cg.shared.global [%0], [%1], 16;" :: "r"(dst), "l"(src));
}
static __device__ __forceinline__ void cp_commit() {
    asm volatile("cp.async.commit_group;");
}
static __device__ __forceinline__ void cp_wait1() {
    asm volatile("cp.async.wait_group 1;" ::: "memory");
}
static __device__ __forceinline__ void cp_wait0() {
    asm volatile("cp.async.wait_group 0;" ::: "memory");
}
static __device__ __forceinline__ void ldm_x4(uint32_t& r0, uint32_t& r1,
                                              uint32_t& r2, uint32_t& r3, uint32_t a) {
    asm volatile("ldmatrix.sync.aligned.m8n8.x4.shared.b16 {%0,%1,%2,%3}, [%4];"
                 : "=r"(r0), "=r"(r1), "=r"(r2), "=r"(r3) : "r"(a));
}
static __device__ __forceinline__ void ldm_x4_t(uint32_t& r0, uint32_t& r1,
                                                uint32_t& r2, uint32_t& r3, uint32_t a) {
    asm volatile("ldmatrix.sync.aligned.m8n8.x4.trans.shared.b16 {%0,%1,%2,%3}, [%4];"
                 : "=r"(r0), "=r"(r1), "=r"(r2), "=r"(r3) : "r"(a));
}
static __device__ __forceinline__ void mma_f16(float* d, const uint32_t* a,
                                               const uint32_t* b) {
    asm volatile(
        "mma.sync.aligned.m16n8k16.row.col.f32.f16.f16.f32 "
        "{%0,%1,%2,%3}, {%4,%5,%6,%7}, {%8,%9}, {%0,%1,%2,%3};"
        : "+f"(d[0]), "+f"(d[1]), "+f"(d[2]), "+f"(d[3])
        : "r"(a[0]), "r"(a[1]), "r"(a[2]), "r"(a[3]), "r"(b[0]), "r"(b[1]));
}
static __device__ __forceinline__ uint32_t packh(float x, float y) {
    __half2 t = __floats2half2_rn(x, y);
    return *reinterpret_cast<uint32_t*>(&t);
}

// ---------------------------------------------------------------------------
// fp32 -> fp16 casts
// ---------------------------------------------------------------------------
__global__ __launch_bounds__(256) void cast_query(const float* __restrict__ src, int n)
{
    int i = blockIdx.x * blockDim.x + threadIdx.x;
    int stride = gridDim.x * blockDim.x;
    for (; 4 * i < n; i += stride) {
        float4 v = ((const float4*)src)[i];
        ((uint32_t*)(g_A16 + (size_t)4 * i))[0] = packh(v.x, v.y);
        ((uint32_t*)(g_A16 + (size_t)4 * i))[1] = packh(v.z, v.w);
    }
}

__global__ __launch_bounds__(256) void cast_weights(
    const float* __restrict__ qw, const float* __restrict__ kw,
    const float* __restrict__ vw, const float* __restrict__ ow)
{
    const int w = blockIdx.y;
    const float* src = (w == 0) ? qw : (w == 1) ? kw : (w == 2) ? vw : ow;
    __half* dst = g_W16 + (size_t)w * WELEM;
    int i = blockIdx.x * blockDim.x + threadIdx.x;
    int stride = gridDim.x * blockDim.x;
    for (; 4 * i < WELEM; i += stride) {
        float4 v = ((const float4*)src)[i];
        ((uint32_t*)(dst + (size_t)4 * i))[0] = packh(v.x, v.y);
        ((uint32_t*)(dst + (size_t)4 * i))[1] = packh(v.z, v.w);
    }
}

// ---------------------------------------------------------------------------
// fp16 GEMM core: tile 128x128, BK=32, 3-stage single-barrier pipeline.
// ---------------------------------------------------------------------------
#define GTIL 8192
#define GSTG 16384

template<bool QKV>
__global__ __launch_bounds__(256) void gemm_f16(
    const float* __restrict__ b0, const float* __restrict__ b1,
    const float* __restrict__ b2, float* __restrict__ Copt, float scale)
{
    extern __shared__ __align__(16) char smem[];
    const uint32_t sbase = smem_u32(smem);

    const int tid  = threadIdx.x;
    const int wid  = tid >> 5;
    const int lane = tid & 31;
    const int wm = wid >> 2;
    const int wn = wid & 3;
    const int bm = blockIdx.y * 128;
    const int bn = blockIdx.x * 128;
    const int z  = QKV ? blockIdx.z : 3;

    const __half* Bw = g_W16 + (size_t)z * WELEM;
    const float* bias = QKV ? (z == 0 ? b0 : (z == 1 ? b1 : b2)) : b0;
    const float alpha = (QKV && z == 0) ? scale : 1.0f;

    uint32_t ldst[4]; const __half* lsrc[4];
#pragma unroll
    for (int t = 0; t < 4; t++) {
        int idx = tid + t * 256;
        int tile = idx >> 9;
        int row  = (idx & 511) >> 2;
        int c    = idx & 3;
        int swc  = c ^ ((row >> 1) & 3);
        ldst[t] = (uint32_t)(tile * GTIL + row * 64 + swc * 16);
        lsrc[t] = (tile ? (Bw + (size_t)(bn + row) * 2048)
                        : (g_A16 + (size_t)(bm + row) * 2048)) + c * 8;
    }

    const int frow = lane & 15;
    const int fhal = lane >> 4;
    const int fsw  = (frow >> 1) & 3;
    const uint32_t cof0 = (uint32_t)(((0 + fhal) ^ fsw) * 16);
    const uint32_t cof1 = (uint32_t)(((2 + fhal) ^ fsw) * 16);

    float acc[4][4][4];
#pragma unroll
    for (int i = 0; i < 4; i++)
#pragma unroll
        for (int j = 0; j < 4; j++)
#pragma unroll
            for (int q = 0; q < 4; q++) acc[i][j][q] = 0.0f;

#pragma unroll
    for (int ps = 0; ps < 2; ps++) {
        const uint32_t stg = sbase + (uint32_t)(ps * GSTG);
#pragma unroll
        for (int t = 0; t < 4; t++)
            cp_async16(stg + ldst[t], lsrc[t] + ps * 32);
        cp_commit();
    }

    int cur = 0;
    for (int s = 0; s < 64; s++) {
        if (s < 63) cp_wait1(); else cp_wait0();
        __syncthreads();

        if (s + 2 < 64) {
            int nxt2 = cur + 2; if (nxt2 >= 3) nxt2 -= 3;
            const uint32_t stg = sbase + (uint32_t)(nxt2 * GSTG);
#pragma unroll
            for (int t = 0; t < 4; t++)
                cp_async16(stg + ldst[t], lsrc[t] + (s + 2) * 32);
            cp_commit();
        }

        const uint32_t stg = sbase + (uint32_t)(cur * GSTG);
        cur++; if (cur == 3) cur = 0;

#pragma unroll
        for (int ks = 0; ks < 2; ks++) {
            const uint32_t cof = ks ? cof1 : cof0;
            uint32_t bf[4][2];
#pragma unroll
            for (int pair = 0; pair < 2; pair++) {
                uint32_t r0, r1, r2, r3;
                ldm_x4(r0, r1, r2, r3,
                       stg + GTIL + (uint32_t)((wn * 32 + pair * 16 + frow) * 64) + cof);
                bf[2 * pair][0] = r0; bf[2 * pair][1] = r2;
                bf[2 * pair + 1][0] = r1; bf[2 * pair + 1][1] = r3;
            }
#pragma unroll
            for (int mf = 0; mf < 4; mf++) {
                uint32_t af[4];
                ldm_x4(af[0], af[1], af[2], af[3],
                       stg + (uint32_t)((wm * 64 + mf * 16 + frow) * 64) + cof);
#pragma unroll
                for (int nf = 0; nf < 4; nf++)
                    mma_f16(acc[mf][nf], af, bf[nf]);
            }
        }
    }

    if (!QKV) {
#pragma unroll
        for (int mf = 0; mf < 4; mf++) {
#pragma unroll
            for (int nf = 0; nf < 4; nf++) {
                const int row0 = bm + wm * 64 + mf * 16 + (lane >> 2);
                const int col  = bn + wn * 32 + nf * 8 + (lane & 3) * 2;
                float2 bv = *(const float2*)&bias[col];
                float2 o0, o1;
                o0.x = acc[mf][nf][0] + bv.x;
                o0.y = acc[mf][nf][1] + bv.y;
                o1.x = acc[mf][nf][2] + bv.x;
                o1.y = acc[mf][nf][3] + bv.y;
                *(float2*)&Copt[(size_t)row0 * 2048 + col] = o0;
                *(float2*)&Copt[(size_t)(row0 + 8) * 2048 + col] = o1;
            }
        }
    } else {
        __half* dst = (z == 0) ? g_Q16 : (z == 1) ? g_K16 : g_V16;
#pragma unroll
        for (int mf = 0; mf < 4; mf++) {
#pragma unroll
            for (int nf = 0; nf < 4; nf++) {
                const int row0 = bm + wm * 64 + mf * 16 + (lane >> 2);
                const int col  = bn + wn * 32 + nf * 8 + (lane & 3) * 2;
                float2 bv = *(const float2*)&bias[col];
                *(uint32_t*)&dst[(size_t)row0 * 2048 + col] =
                    packh(alpha * (acc[mf][nf][0] + bv.x),
                          alpha * (acc[mf][nf][1] + bv.y));
                *(uint32_t*)&dst[(size_t)(row0 + 8) * 2048 + col] =
                    packh(alpha * (acc[mf][nf][2] + bv.x),
                          alpha * (acc[mf][nf][3] + bv.y));
            }
        }
    }
}

// ---------------------------------------------------------------------------
// fp16 HMMA causal flash attention, 128 threads (4 warps), 3 CTAs/SM.
// Q tile resident in smem (re-ldmatrix'd per K-chunk) to cut registers.
// K/V separate commit groups so QK^T overlaps the V load.
// Heavy-first CTA order: qt = gridDim.x-1-blockIdx.x.
// ---------------------------------------------------------------------------
#define ASR 272                     // smem row stride bytes (136 halves)
#define AK16 17408
#define AV16 26112
#define ATT_SMEM 34816

__global__ __launch_bounds__(128, 3) void flash_attn_f16()
{
    extern __shared__ __align__(16) char smem[];
    const uint32_t sb = smem_u32(smem);
    const int tid  = threadIdx.x;
    const int wid  = tid >> 5;
    const int lane = tid & 31;
    const int qt = gridDim.x - 1 - blockIdx.x;   // heavy-first
    const int bb = blockIdx.y;
    const int n  = bb / H_;
    const int h  = bb % H_;
    const int q0 = qt * 64;
    const int wr = q0 + wid * 16;
    const int colbase = h * DH;
    const int lr = lane >> 2;
    const int lc = lane & 3;
    const int frow = lane & 15;
    const int fhal = lane >> 4;

    // Prologue: Q tile (64 rows) -> smem, own commit group.
#pragma unroll
    for (int i = 0; i < 8; i++) {
        int c = tid + i * 128;
        int row = c >> 4;
        int seg = c & 15;
        cp_async16(sb + row * ASR + seg * 16,
                   g_Q16 + ((size_t)(q0 + row) * NB + n) * 2048 + colbase + seg * 8);
    }
    cp_commit();

    float oacc[16][4];
#pragma unroll
    for (int f = 0; f < 16; f++)
#pragma unroll
        for (int q = 0; q < 4; q++) oacc[f][q] = 0.0f;
    float m_run[2] = {-1e30f, -1e30f};
    float l_run[2] = {0.0f, 0.0f};

    const int jt_max = 2 * qt + 1;
    for (int jt = 0; jt <= jt_max; jt++) {
        const int k0 = jt * 32;
        __syncthreads();   // prior tile's smem readers done

#pragma unroll
        for (int i = 0; i < 4; i++) {
            int c = tid + i * 128;
            int row = c >> 4;
            int seg = c & 15;
            cp_async16(sb + AK16 + row * ASR + seg * 16,
                       g_K16 + ((size_t)(k0 + row) * NB + n) * 2048 + colbase + seg * 8);
        }
        cp_commit();
#pragma unroll
        for (int i = 0; i < 4; i++) {
            int c = tid + i * 128;
            int row = c >> 4;
            int seg = c & 15;
            cp_async16(sb + AV16 + row * ASR + seg * 16,
                       g_V16 + ((size_t)(k0 + row) * NB + n) * 2048 + colbase + seg * 8);
        }
        cp_commit();

        cp_wait1();        // Q + K ready (V may still be in flight)
        __syncthreads();

        const bool active = (k0 <= wr + 15);
        uint32_t ph[2][4];

        if (active) {
            float sacc[4][4];
#pragma unroll
            for (int j = 0; j < 4; j++)
#pragma unroll
                for (int q = 0; q < 4; q++) sacc[j][q] = 0.0f;

#pragma unroll
            for (int t = 0; t < 8; t++) {
                // Q fragment from smem (A-operand layout)
                uint32_t af[4];
                ldm_x4(af[0], af[1], af[2], af[3],
                       sb + (uint32_t)((wid * 16 + frow) * ASR) + 32 * t + (fhal << 4));
                uint32_t kf[4][2];
#pragma unroll
                for (int g = 0; g < 2; g++) {
                    uint32_t row = (uint32_t)((lane & 7) + ((lane >> 4) << 3) + 16 * g);
                    uint32_t a = sb + AK16 + row * ASR + 32 * t + (((lane >> 3) & 1) << 4);
                    uint32_t r0, r1, r2, r3;
                    ldm_x4(r0, r1, r2, r3, a);
                    kf[2 * g][0] = r0; kf[2 * g][1] = r1;
                    kf[2 * g + 1][0] = r2; kf[2 * g + 1][1] = r3;
                }
#pragma unroll
                for (int j = 0; j < 4; j++)
                    mma_f16(sacc[j], af, kf[j]);
            }

            if (k0 + 31 > wr) {
                const int r0a = wr + lr, r1a = r0a + 8;
#pragma unroll
                for (int j = 0; j < 4; j++) {
                    int kc = k0 + 8 * j + 2 * lc;
                    if (kc > r0a)     sacc[j][0] = -1e30f;
                    if (kc + 1 > r0a) sacc[j][1] = -1e30f;
                    if (kc > r1a)     sacc[j][2] = -1e30f;
                    if (kc + 1 > r1a) sacc[j][3] = -1e30f;
                }
            }

#pragma unroll
            for (int r = 0; r < 2; r++) {
                float mt = -1e30f;
#pragma unroll
                for (int j = 0; j < 4; j++)
                    mt = fmaxf(mt, fmaxf(sacc[j][2 * r], sacc[j][2 * r + 1]));
                mt = fmaxf(mt, __shfl_xor_sync(0xffffffffu, mt, 1));
                mt = fmaxf(mt, __shfl_xor_sync(0xffffffffu, mt, 2));
                float mnew = fmaxf(m_run[r], mt);
                float corr = __expf(m_run[r] - mnew);
                m_run[r] = mnew;
                float rs = 0.0f;
#pragma unroll
                for (int j = 0; j < 4; j++) {
                    sacc[j][2 * r]     = __expf(sacc[j][2 * r] - mnew);
                    sacc[j][2 * r + 1] = __expf(sacc[j][2 * r + 1] - mnew);
                    rs += sacc[j][2 * r] + sacc[j][2 * r + 1];
                }
                rs += __shfl_xor_sync(0xffffffffu, rs, 1);
                rs += __shfl_xor_sync(0xffffffffu, rs, 2);
                l_run[r] = l_run[r] * corr + rs;
#pragma unroll
                for (int f = 0; f < 16; f++) {
                    oacc[f][2 * r]     *= corr;
                    oacc[f][2 * r + 1] *= corr;
                }
            }

#pragma unroll
            for (int t2 = 0; t2 < 2; t2++) {
                const float* s0 = sacc[2 * t2];
                const float* s1 = sacc[2 * t2 + 1];
                ph[t2][0] = packh(s0[0], s0[1]);
                ph[t2][1] = packh(s0[2], s0[3]);
                ph[t2][2] = packh(s1[0], s1[1]);
                ph[t2][3] = packh(s1[2], s1[3]);
            }
        }

        cp_wait0();        // V ready
        __syncthreads();

        if (active) {
#pragma unroll
            for (int t2 = 0; t2 < 2; t2++) {
                uint32_t row = (uint32_t)((lane & 7) + (((lane >> 3) & 1) << 3) + 16 * t2);
#pragma unroll
                for (int g = 0; g < 8; g++) {
                    uint32_t col = (uint32_t)(16 * g + ((lane >> 4) << 3));
                    uint32_t a = sb + AV16 + row * ASR + col * 2;
                    uint32_t r0, r1, r2, r3;
                    ldm_x4_t(r0, r1, r2, r3, a);
                    uint32_t v0[2] = {r0, r1}, v1[2] = {r2, r3};
                    mma_f16(oacc[2 * g],     ph[t2], v0);
                    mma_f16(oacc[2 * g + 1], ph[t2], v1);
                }
            }
        }
    }

    const float inv0 = 1.0f / l_run[0];
    const float inv1 = 1.0f / l_run[1];
    const size_t base0 = ((size_t)(wr + lr) * NB + n) * 2048 + colbase;
    const size_t base1 = ((size_t)(wr + lr + 8) * NB + n) * 2048 + colbase;
#pragma unroll
    for (int f = 0; f < 16; f++) {
        const int c = 8 * f + 2 * lc;
        *(uint32_t*)&g_A16[base0 + c] = packh(oacc[f][0] * inv0, oacc[f][1] * inv0);
        *(uint32_t*)&g_A16[base1 + c] = packh(oacc[f][2] * inv1, oacc[f][3] * inv1);
    }
}

// ---------------------------------------------------------------------------
extern "C" void kernel_launch(void* const* d_in, const int* in_sizes, int n_in,
                              void* d_out, int out_size)
{
    (void)in_sizes; (void)n_in; (void)out_size;
    const float* query = (const float*)d_in[0];
    const float* qw    = (const float*)d_in[1];
    const float* qb    = (const float*)d_in[2];
    const float* kw    = (const float*)d_in[3];
    const float* kb    = (const float*)d_in[4];
    const float* vw    = (const float*)d_in[5];
    const float* vb    = (const float*)d_in[6];
    const float* ow    = (const float*)d_in[7];
    const float* ob    = (const float*)d_in[8];
    float* out = (float*)d_out;

    const float scale = 0.08838834764831845f;  // 1/sqrt(128)
    const int nA = ROWS * I_;

    cast_query<<<nA / 1024, 256>>>(query, nA);
    cast_weights<<<dim3(WELEM / 1024, 4), 256>>>(qw, kw, vw, ow);

    gemm_f16<true><<<dim3(16, 32, 3), 256, 3 * GSTG>>>(qb, kb, vb, nullptr, scale);

    flash_attn_f16<<<dim3(L_ / 64, NB * H_), 128, ATT_SMEM>>>();

    gemm_f16<false><<<dim3(16, 32, 1), 256, 3 * GSTG>>>(ob, nullptr, nullptr, out, 1.0f);
}

// round 14
// speedup vs baseline: 8.2451x; 1.0655x over previous
// v14: attention Bk=64, fully swizzled 48KB Q/K/V smem (no padding),
//      3 CTAs/SM target; everything else unchanged from v13.
#include <cuda_runtime.h>
#include <cuda_fp16.h>
#include <stdint.h>
#include <math.h>

#define L_    2048
#define NB    2
#define E_    2048
#define I_    2048
#define H_    16
#define DH    128
#define ROWS  (L_*NB)        // 4096
#define WELEM (I_*E_)        // 4194304

__device__ __half g_A16[(size_t)ROWS * I_];     // GEMM A input (query, then ctx)
__device__ __half g_W16[(size_t)4 * WELEM];     // weights fp16
__device__ __half g_Q16[(size_t)ROWS * I_];
__device__ __half g_K16[(size_t)ROWS * I_];
__device__ __half g_V16[(size_t)ROWS * I_];

// ---------------------------------------------------------------------------
static __device__ __forceinline__ uint32_t smem_u32(const void* p) {
    uint32_t a;
    asm("{ .reg .u64 t; cvta.to.shared.u64 t, %1; cvt.u32.u64 %0, t; }"
        : "=r"(a) : "l"(p));
    return a;
}
static __device__ __forceinline__ void cp_async16(uint32_t dst, const void* src) {
    asm volatile("cp.async.cg.shared.global [%0], [%1], 16;" :: "r"(dst), "l"(src));
}
static __device__ __forceinline__ void cp_commit() {
    asm volatile("cp.async.commit_group;");
}
static __device__ __forceinline__ void cp_wait1() {
    asm volatile("cp.async.wait_group 1;" ::: "memory");
}
static __device__ __forceinline__ void cp_wait0() {
    asm volatile("cp.async.wait_group 0;" ::: "memory");
}
static __device__ __forceinline__ void ldm_x4(uint32_t& r0, uint32_t& r1,
                                              uint32_t& r2, uint32_t& r3, uint32_t a) {
    asm volatile("ldmatrix.sync.aligned.m8n8.x4.shared.b16 {%0,%1,%2,%3}, [%4];"
                 : "=r"(r0), "=r"(r1), "=r"(r2), "=r"(r3) : "r"(a));
}
static __device__ __forceinline__ void ldm_x4_t(uint32_t& r0, uint32_t& r1,
                                                uint32_t& r2, uint32_t& r3, uint32_t a) {
    asm volatile("ldmatrix.sync.aligned.m8n8.x4.trans.shared.b16 {%0,%1,%2,%3}, [%4];"
                 : "=r"(r0), "=r"(r1), "=r"(r2), "=r"(r3) : "r"(a));
}
static __device__ __forceinline__ void mma_f16(float* d, const uint32_t* a,
                                               const uint32_t* b) {
    asm volatile(
        "mma.sync.aligned.m16n8k16.row.col.f32.f16.f16.f32 "
        "{%0,%1,%2,%3}, {%4,%5,%6,%7}, {%8,%9}, {%0,%1,%2,%3};"
        : "+f"(d[0]), "+f"(d[1]), "+f"(d[2]), "+f"(d[3])
        : "r"(a[0]), "r"(a[1]), "r"(a[2]), "r"(a[3]), "r"(b[0]), "r"(b[1]));
}
static __device__ __forceinline__ uint32_t packh(float x, float y) {
    __half2 t = __floats2half2_rn(x, y);
    return *reinterpret_cast<uint32_t*>(&t);
}

// ---------------------------------------------------------------------------
// fp32 -> fp16 casts
// ---------------------------------------------------------------------------
__global__ __launch_bounds__(256) void cast_query(const float* __restrict__ src, int n)
{
    int i = blockIdx.x * blockDim.x + threadIdx.x;
    int stride = gridDim.x * blockDim.x;
    for (; 4 * i < n; i += stride) {
        float4 v = ((const float4*)src)[i];
        ((uint32_t*)(g_A16 + (size_t)4 * i))[0] = packh(v.x, v.y);
        ((uint32_t*)(g_A16 + (size_t)4 * i))[1] = packh(v.z, v.w);
    }
}

__global__ __launch_bounds__(256) void cast_weights(
    const float* __restrict__ qw, const float* __restrict__ kw,
    const float* __restrict__ vw, const float* __restrict__ ow)
{
    const int w = blockIdx.y;
    const float* src = (w == 0) ? qw : (w == 1) ? kw : (w == 2) ? vw : ow;
    __half* dst = g_W16 + (size_t)w * WELEM;
    int i = blockIdx.x * blockDim.x + threadIdx.x;
    int stride = gridDim.x * blockDim.x;
    for (; 4 * i < WELEM; i += stride) {
        float4 v = ((const float4*)src)[i];
        ((uint32_t*)(dst + (size_t)4 * i))[0] = packh(v.x, v.y);
        ((uint32_t*)(dst + (size_t)4 * i))[1] = packh(v.z, v.w);
    }
}

// ---------------------------------------------------------------------------
// fp16 GEMM core: tile 128x128, BK=32, 3-stage single-barrier pipeline.
// (unchanged from v13 — near the mma.sync path ceiling)
// ---------------------------------------------------------------------------
#define GTIL 8192
#define GSTG 16384

template<bool QKV>
__global__ __launch_bounds__(256) void gemm_f16(
    const float* __restrict__ b0, const float* __restrict__ b1,
    const float* __restrict__ b2, float* __restrict__ Copt, float scale)
{
    extern __shared__ __align__(16) char smem[];
    const uint32_t sbase = smem_u32(smem);

    const int tid  = threadIdx.x;
    const int wid  = tid >> 5;
    const int lane = tid & 31;
    const int wm = wid >> 2;
    const int wn = wid & 3;
    const int bm = blockIdx.y * 128;
    const int bn = blockIdx.x * 128;
    const int z  = QKV ? blockIdx.z : 3;

    const __half* Bw = g_W16 + (size_t)z * WELEM;
    const float* bias = QKV ? (z == 0 ? b0 : (z == 1 ? b1 : b2)) : b0;
    const float alpha = (QKV && z == 0) ? scale : 1.0f;

    uint32_t ldst[4]; const __half* lsrc[4];
#pragma unroll
    for (int t = 0; t < 4; t++) {
        int idx = tid + t * 256;
        int tile = idx >> 9;
        int row  = (idx & 511) >> 2;
        int c    = idx & 3;
        int swc  = c ^ ((row >> 1) & 3);
        ldst[t] = (uint32_t)(tile * GTIL + row * 64 + swc * 16);
        lsrc[t] = (tile ? (Bw + (size_t)(bn + row) * 2048)
                        : (g_A16 + (size_t)(bm + row) * 2048)) + c * 8;
    }

    const int frow = lane & 15;
    const int fhal = lane >> 4;
    const int fsw  = (frow >> 1) & 3;
    const uint32_t cof0 = (uint32_t)(((0 + fhal) ^ fsw) * 16);
    const uint32_t cof1 = (uint32_t)(((2 + fhal) ^ fsw) * 16);

    float acc[4][4][4];
#pragma unroll
    for (int i = 0; i < 4; i++)
#pragma unroll
        for (int j = 0; j < 4; j++)
#pragma unroll
            for (int q = 0; q < 4; q++) acc[i][j][q] = 0.0f;

#pragma unroll
    for (int ps = 0; ps < 2; ps++) {
        const uint32_t stg = sbase + (uint32_t)(ps * GSTG);
#pragma unroll
        for (int t = 0; t < 4; t++)
            cp_async16(stg + ldst[t], lsrc[t] + ps * 32);
        cp_commit();
    }

    int cur = 0;
    for (int s = 0; s < 64; s++) {
        if (s < 63) cp_wait1(); else cp_wait0();
        __syncthreads();

        if (s + 2 < 64) {
            int nxt2 = cur + 2; if (nxt2 >= 3) nxt2 -= 3;
            const uint32_t stg = sbase + (uint32_t)(nxt2 * GSTG);
#pragma unroll
            for (int t = 0; t < 4; t++)
                cp_async16(stg + ldst[t], lsrc[t] + (s + 2) * 32);
            cp_commit();
        }

        const uint32_t stg = sbase + (uint32_t)(cur * GSTG);
        cur++; if (cur == 3) cur = 0;

#pragma unroll
        for (int ks = 0; ks < 2; ks++) {
            const uint32_t cof = ks ? cof1 : cof0;
            uint32_t bf[4][2];
#pragma unroll
            for (int pair = 0; pair < 2; pair++) {
                uint32_t r0, r1, r2, r3;
                ldm_x4(r0, r1, r2, r3,
                       stg + GTIL + (uint32_t)((wn * 32 + pair * 16 + frow) * 64) + cof);
                bf[2 * pair][0] = r0; bf[2 * pair][1] = r2;
                bf[2 * pair + 1][0] = r1; bf[2 * pair + 1][1] = r3;
            }
#pragma unroll
            for (int mf = 0; mf < 4; mf++) {
                uint32_t af[4];
                ldm_x4(af[0], af[1], af[2], af[3],
                       stg + (uint32_t)((wm * 64 + mf * 16 + frow) * 64) + cof);
#pragma unroll
                for (int nf = 0; nf < 4; nf++)
                    mma_f16(acc[mf][nf], af, bf[nf]);
            }
        }
    }

    if (!QKV) {
#pragma unroll
        for (int mf = 0; mf < 4; mf++) {
#pragma unroll
            for (int nf = 0; nf < 4; nf++) {
                const int row0 = bm + wm * 64 + mf * 16 + (lane >> 2);
                const int col  = bn + wn * 32 + nf * 8 + (lane & 3) * 2;
                float2 bv = *(const float2*)&bias[col];
                float2 o0, o1;
                o0.x = acc[mf][nf][0] + bv.x;
                o0.y = acc[mf][nf][1] + bv.y;
                o1.x = acc[mf][nf][2] + bv.x;
                o1.y = acc[mf][nf][3] + bv.y;
                *(float2*)&Copt[(size_t)row0 * 2048 + col] = o0;
                *(float2*)&Copt[(size_t)(row0 + 8) * 2048 + col] = o1;
            }
        }
    } else {
        __half* dst = (z == 0) ? g_Q16 : (z == 1) ? g_K16 : g_V16;
#pragma unroll
        for (int mf = 0; mf < 4; mf++) {
#pragma unroll
            for (int nf = 0; nf < 4; nf++) {
                const int row0 = bm + wm * 64 + mf * 16 + (lane >> 2);
                const int col  = bn + wn * 32 + nf * 8 + (lane & 3) * 2;
                float2 bv = *(const float2*)&bias[col];
                *(uint32_t*)&dst[(size_t)row0 * 2048 + col] =
                    packh(alpha * (acc[mf][nf][0] + bv.x),
                          alpha * (acc[mf][nf][1] + bv.y));
                *(uint32_t*)&dst[(size_t)(row0 + 8) * 2048 + col] =
                    packh(alpha * (acc[mf][nf][2] + bv.x),
                          alpha * (acc[mf][nf][3] + bv.y));
            }
        }
    }
}

// ---------------------------------------------------------------------------
// fp16 HMMA causal flash attention: Bq=64, Bk=64, 128 threads (4 warps).
// Q/K/V tiles 64 rows x 128 halves packed at 256B/row with XOR swizzle
// (chunk ^= row&7) -> conflict-free ldmatrix, 3 x 16KB = 48KB exactly.
// K/V separate commit groups; heavy-first CTA order.
// ---------------------------------------------------------------------------
#define QOFF 0
#define KOFF 16384
#define VOFF 32768
#define ATT_SMEM 49152
#define SWA(base, row, ch) ((base) + (uint32_t)((row) * 256 + (((ch) ^ ((row) & 7)) << 4)))

__global__ __launch_bounds__(128, 3) void flash_attn_f16()
{
    extern __shared__ __align__(16) char smem[];
    const uint32_t sb = smem_u32(smem);
    const int tid  = threadIdx.x;
    const int wid  = tid >> 5;
    const int lane = tid & 31;
    const int qt = gridDim.x - 1 - blockIdx.x;   // heavy-first
    const int bb = blockIdx.y;
    const int n  = bb / H_;
    const int h  = bb % H_;
    const int q0 = qt * 64;
    const int wr = q0 + wid * 16;
    const int colbase = h * DH;
    const int lr = lane >> 2;
    const int lc = lane & 3;
    const int frow = lane & 15;
    const int fhal = lane >> 4;

    // Prologue: Q tile (64 rows x 16 chunks) -> smem, own commit group.
#pragma unroll
    for (int i = 0; i < 8; i++) {
        int c = tid + i * 128;
        int row = c >> 4;
        int ch  = c & 15;
        cp_async16(SWA(sb + QOFF, row, ch),
                   g_Q16 + ((size_t)(q0 + row) * NB + n) * 2048 + colbase + ch * 8);
    }
    cp_commit();

    float oacc[16][4];
#pragma unroll
    for (int f = 0; f < 16; f++)
#pragma unroll
        for (int q = 0; q < 4; q++) oacc[f][q] = 0.0f;
    float m_run[2] = {-1e30f, -1e30f};
    float l_run[2] = {0.0f, 0.0f};

    for (int jt = 0; jt <= qt; jt++) {
        const int k0 = jt * 64;
        __syncthreads();   // prior tile's smem readers done

        // K tile (group), then V tile (group)
#pragma unroll
        for (int i = 0; i < 8; i++) {
            int c = tid + i * 128;
            int row = c >> 4;
            int ch  = c & 15;
            cp_async16(SWA(sb + KOFF, row, ch),
                       g_K16 + ((size_t)(k0 + row) * NB + n) * 2048 + colbase + ch * 8);
        }
        cp_commit();
#pragma unroll
        for (int i = 0; i < 8; i++) {
            int c = tid + i * 128;
            int row = c >> 4;
            int ch  = c & 15;
            cp_async16(SWA(sb + VOFF, row, ch),
                       g_V16 + ((size_t)(k0 + row) * NB + n) * 2048 + colbase + ch * 8);
        }
        cp_commit();

        cp_wait1();        // Q + K ready (V may still be in flight)
        __syncthreads();

        const bool active = (k0 <= wr + 15);
        uint32_t ph[4][4];

        if (active) {
            float sacc[8][4];
#pragma unroll
            for (int j = 0; j < 8; j++)
#pragma unroll
                for (int q = 0; q < 4; q++) sacc[j][q] = 0.0f;

#pragma unroll
            for (int t = 0; t < 8; t++) {
                // Q fragment (A layout): row = wid*16+frow, chunk = 2t+fhal
                uint32_t af[4];
                {
                    int row = wid * 16 + frow;
                    ldm_x4(af[0], af[1], af[2], af[3], SWA(sb + QOFF, row, 2 * t + fhal));
                }
                // K fragments (B layout): 8 n8-frags via 4 ldm_x4
                uint32_t kf[8][2];
#pragma unroll
                for (int g = 0; g < 4; g++) {
                    int row = (lane & 7) + ((lane >> 4) << 3) + 16 * g;
                    int ch  = 2 * t + ((lane >> 3) & 1);
                    uint32_t r0, r1, r2, r3;
                    ldm_x4(r0, r1, r2, r3, SWA(sb + KOFF, row, ch));
                    kf[2 * g][0] = r0; kf[2 * g][1] = r1;
                    kf[2 * g + 1][0] = r2; kf[2 * g + 1][1] = r3;
                }
#pragma unroll
                for (int j = 0; j < 8; j++)
                    mma_f16(sacc[j], af, kf[j]);
            }

            // Causal mask (tile straddles diagonal when k0+63 > wr)
            if (k0 + 63 > wr) {
                const int r0a = wr + lr, r1a = r0a + 8;
#pragma unroll
                for (int j = 0; j < 8; j++) {
                    int kc = k0 + 8 * j + 2 * lc;
                    if (kc > r0a)     sacc[j][0] = -1e30f;
                    if (kc + 1 > r0a) sacc[j][1] = -1e30f;
                    if (kc > r1a)     sacc[j][2] = -1e30f;
                    if (kc + 1 > r1a) sacc[j][3] = -1e30f;
                }
            }

            // Online softmax (rows lr, lr+8; reduce across lanes xor 1,2)
#pragma unroll
            for (int r = 0; r < 2; r++) {
                float mt = -1e30f;
#pragma unroll
                for (int j = 0; j < 8; j++)
                    mt = fmaxf(mt, fmaxf(sacc[j][2 * r], sacc[j][2 * r + 1]));
                mt = fmaxf(mt, __shfl_xor_sync(0xffffffffu, mt, 1));
                mt = fmaxf(mt, __shfl_xor_sync(0xffffffffu, mt, 2));
                float mnew = fmaxf(m_run[r], mt);
                float corr = __expf(m_run[r] - mnew);
                m_run[r] = mnew;
                float rs = 0.0f;
#pragma unroll
                for (int j = 0; j < 8; j++) {
                    sacc[j][2 * r]     = __expf(sacc[j][2 * r] - mnew);
                    sacc[j][2 * r + 1] = __expf(sacc[j][2 * r + 1] - mnew);
                    rs += sacc[j][2 * r] + sacc[j][2 * r + 1];
                }
                rs += __shfl_xor_sync(0xffffffffu, rs, 1);
                rs += __shfl_xor_sync(0xffffffffu, rs, 2);
                l_run[r] = l_run[r] * corr + rs;
#pragma unroll
                for (int f = 0; f < 16; f++) {
                    oacc[f][2 * r]     *= corr;
                    oacc[f][2 * r + 1] *= corr;
                }
            }

            // P fragments (A-operand layout): t2 = kv 16-chunk 0..3
#pragma unroll
            for (int t2 = 0; t2 < 4; t2++) {
                const float* s0 = sacc[2 * t2];
                const float* s1 = sacc[2 * t2 + 1];
                ph[t2][0] = packh(s0[0], s0[1]);
                ph[t2][1] = packh(s0[2], s0[3]);
                ph[t2][2] = packh(s1[0], s1[1]);
                ph[t2][3] = packh(s1[2], s1[3]);
            }
        }

        cp_wait0();        // V ready
        __syncthreads();

        if (active) {
#pragma unroll
            for (int t2 = 0; t2 < 4; t2++) {
                int row = (lane & 7) + (((lane >> 3) & 1) << 3) + 16 * t2;
#pragma unroll
                for (int g = 0; g < 8; g++) {
                    int ch = 2 * g + (lane >> 4);
                    uint32_t r0, r1, r2, r3;
                    ldm_x4_t(r0, r1, r2, r3, SWA(sb + VOFF, row, ch));
                    uint32_t v0[2] = {r0, r1}, v1[2] = {r2, r3};
                    mma_f16(oacc[2 * g],     ph[t2], v0);
                    mma_f16(oacc[2 * g + 1], ph[t2], v1);
                }
            }
        }
    }

    // Epilogue: normalize, cast fp16, store into out-proj A buffer
    const float inv0 = 1.0f / l_run[0];
    const float inv1 = 1.0f / l_run[1];
    const size_t base0 = ((size_t)(wr + lr) * NB + n) * 2048 + colbase;
    const size_t base1 = ((size_t)(wr + lr + 8) * NB + n) * 2048 + colbase;
#pragma unroll
    for (int f = 0; f < 16; f++) {
        const int c = 8 * f + 2 * lc;
        *(uint32_t*)&g_A16[base0 + c] = packh(oacc[f][0] * inv0, oacc[f][1] * inv0);
        *(uint32_t*)&g_A16[base1 + c] = packh(oacc[f][2] * inv1, oacc[f][3] * inv1);
    }
}

// ---------------------------------------------------------------------------
extern "C" void kernel_launch(void* const* d_in, const int* in_sizes, int n_in,
                              void* d_out, int out_size)
{
    (void)in_sizes; (void)n_in; (void)out_size;
    const float* query = (const float*)d_in[0];
    const float* qw    = (const float*)d_in[1];
    const float* qb    = (const float*)d_in[2];
    const float* kw    = (const float*)d_in[3];
    const float* kb    = (const float*)d_in[4];
    const float* vw    = (const float*)d_in[5];
    const float* vb    = (const float*)d_in[6];
    const float* ow    = (const float*)d_in[7];
    const float* ob    = (const float*)d_in[8];
    float* out = (float*)d_out;

    const float scale = 0.08838834764831845f;  // 1/sqrt(128)
    const int nA = ROWS * I_;

    cast_query<<<nA / 1024, 256>>>(query, nA);
    cast_weights<<<dim3(WELEM / 1024, 4), 256>>>(qw, kw, vw, ow);

    gemm_f16<true><<<dim3(16, 32, 3), 256, 3 * GSTG>>>(qb, kb, vb, nullptr, scale);

    flash_attn_f16<<<dim3(L_ / 64, NB * H_), 128, ATT_SMEM>>>();

    gemm_f16<false><<<dim3(16, 32, 1), 256, 3 * GSTG>>>(ob, nullptr, nullptr, out, 1.0f);
}

// round 15
// speedup vs baseline: 8.3132x; 1.0083x over previous
// v15: exp2-folded softmax + rescale-skip + kf interleave (reg trim) +
//      single fused cast kernel. GEMMs unchanged (at mma.sync ceiling).
#include <cuda_runtime.h>
#include <cuda_fp16.h>
#include <stdint.h>
#include <math.h>

#define L_    2048
#define NB    2
#define E_    2048
#define I_    2048
#define H_    16
#define DH    128
#define ROWS  (L_*NB)        // 4096
#define WELEM (I_*E_)        // 4194304

__device__ __half g_A16[(size_t)ROWS * I_];     // GEMM A input (query, then ctx)
__device__ __half g_W16[(size_t)4 * WELEM];     // weights fp16 (contiguous)
__device__ __half g_Q16[(size_t)ROWS * I_];
__device__ __half g_K16[(size_t)ROWS * I_];
__device__ __half g_V16[(size_t)ROWS * I_];

// ---------------------------------------------------------------------------
static __device__ __forceinline__ uint32_t smem_u32(const void* p) {
    uint32_t a;
    asm("{ .reg .u64 t; cvta.to.shared.u64 t, %1; cvt.u32.u64 %0, t; }"
        : "=r"(a) : "l"(p));
    return a;
}
static __device__ __forceinline__ void cp_async16(uint32_t dst, const void* src) {
    asm volatile("cp.async.cg.shared.global [%0], [%1], 16;" :: "r"(dst), "l"(src));
}
static __device__ __forceinline__ void cp_commit() {
    asm volatile("cp.async.commit_group;");
}
static __device__ __forceinline__ void cp_wait1() {
    asm volatile("cp.async.wait_group 1;" ::: "memory");
}
static __device__ __forceinline__ void cp_wait0() {
    asm volatile("cp.async.wait_group 0;" ::: "memory");
}
static __device__ __forceinline__ void ldm_x4(uint32_t& r0, uint32_t& r1,
                                              uint32_t& r2, uint32_t& r3, uint32_t a) {
    asm volatile("ldmatrix.sync.aligned.m8n8.x4.shared.b16 {%0,%1,%2,%3}, [%4];"
                 : "=r"(r0), "=r"(r1), "=r"(r2), "=r"(r3) : "r"(a));
}
static __device__ __forceinline__ void ldm_x4_t(uint32_t& r0, uint32_t& r1,
                                                uint32_t& r2, uint32_t& r3, uint32_t a) {
    asm volatile("ldmatrix.sync.aligned.m8n8.x4.trans.shared.b16 {%0,%1,%2,%3}, [%4];"
                 : "=r"(r0), "=r"(r1), "=r"(r2), "=r"(r3) : "r"(a));
}
static __device__ __forceinline__ void mma_f16(float* d, const uint32_t* a,
                                               const uint32_t* b) {
    asm volatile(
        "mma.sync.aligned.m16n8k16.row.col.f32.f16.f16.f32 "
        "{%0,%1,%2,%3}, {%4,%5,%6,%7}, {%8,%9}, {%0,%1,%2,%3};"
        : "+f"(d[0]), "+f"(d[1]), "+f"(d[2]), "+f"(d[3])
        : "r"(a[0]), "r"(a[1]), "r"(a[2]), "r"(a[3]), "r"(b[0]), "r"(b[1]));
}
static __device__ __forceinline__ uint32_t packh(float x, float y) {
    __half2 t = __floats2half2_rn(x, y);
    return *reinterpret_cast<uint32_t*>(&t);
}

// ---------------------------------------------------------------------------
// Fused fp32 -> fp16 cast over [query | qw | kw | vw | ow].
// g_W16 is contiguous, so dst is a simple split; src selected by range.
// ---------------------------------------------------------------------------
__global__ __launch_bounds__(256) void cast_all(
    const float* __restrict__ query, const float* __restrict__ qw,
    const float* __restrict__ kw, const float* __restrict__ vw,
    const float* __restrict__ ow)
{
    const int i = blockIdx.x * blockDim.x + threadIdx.x;
    const size_t e = (size_t)4 * i;          // element index in concat space
    const size_t nA = (size_t)ROWS * I_;     // 8388608
    const float* src;
    __half* dst;
    if (e < nA) {
        src = query + e;
        dst = g_A16 + e;
    } else {
        size_t r = e - nA;
        dst = g_W16 + r;
        int w = (int)(r >> 22);              // WELEM = 2^22
        size_t off = r & (WELEM - 1);
        src = ((w == 0) ? qw : (w == 1) ? kw : (w == 2) ? vw : ow) + off;
    }
    float4 v = *(const float4*)src;
    ((uint32_t*)dst)[0] = packh(v.x, v.y);
    ((uint32_t*)dst)[1] = packh(v.z, v.w);
}

// ---------------------------------------------------------------------------
// fp16 GEMM core: tile 128x128, BK=32, 3-stage single-barrier pipeline.
// (unchanged — at the mma.sync path ceiling)
// ---------------------------------------------------------------------------
#define GTIL 8192
#define GSTG 16384

template<bool QKV>
__global__ __launch_bounds__(256) void gemm_f16(
    const float* __restrict__ b0, const float* __restrict__ b1,
    const float* __restrict__ b2, float* __restrict__ Copt, float scale)
{
    extern __shared__ __align__(16) char smem[];
    const uint32_t sbase = smem_u32(smem);

    const int tid  = threadIdx.x;
    const int wid  = tid >> 5;
    const int lane = tid & 31;
    const int wm = wid >> 2;
    const int wn = wid & 3;
    const int bm = blockIdx.y * 128;
    const int bn = blockIdx.x * 128;
    const int z  = QKV ? blockIdx.z : 3;

    const __half* Bw = g_W16 + (size_t)z * WELEM;
    const float* bias = QKV ? (z == 0 ? b0 : (z == 1 ? b1 : b2)) : b0;
    const float alpha = (QKV && z == 0) ? scale : 1.0f;

    uint32_t ldst[4]; const __half* lsrc[4];
#pragma unroll
    for (int t = 0; t < 4; t++) {
        int idx = tid + t * 256;
        int tile = idx >> 9;
        int row  = (idx & 511) >> 2;
        int c    = idx & 3;
        int swc  = c ^ ((row >> 1) & 3);
        ldst[t] = (uint32_t)(tile * GTIL + row * 64 + swc * 16);
        lsrc[t] = (tile ? (Bw + (size_t)(bn + row) * 2048)
                        : (g_A16 + (size_t)(bm + row) * 2048)) + c * 8;
    }

    const int frow = lane & 15;
    const int fhal = lane >> 4;
    const int fsw  = (frow >> 1) & 3;
    const uint32_t cof0 = (uint32_t)(((0 + fhal) ^ fsw) * 16);
    const uint32_t cof1 = (uint32_t)(((2 + fhal) ^ fsw) * 16);

    float acc[4][4][4];
#pragma unroll
    for (int i = 0; i < 4; i++)
#pragma unroll
        for (int j = 0; j < 4; j++)
#pragma unroll
            for (int q = 0; q < 4; q++) acc[i][j][q] = 0.0f;

#pragma unroll
    for (int ps = 0; ps < 2; ps++) {
        const uint32_t stg = sbase + (uint32_t)(ps * GSTG);
#pragma unroll
        for (int t = 0; t < 4; t++)
            cp_async16(stg + ldst[t], lsrc[t] + ps * 32);
        cp_commit();
    }

    int cur = 0;
    for (int s = 0; s < 64; s++) {
        if (s < 63) cp_wait1(); else cp_wait0();
        __syncthreads();

        if (s + 2 < 64) {
            int nxt2 = cur + 2; if (nxt2 >= 3) nxt2 -= 3;
            const uint32_t stg = sbase + (uint32_t)(nxt2 * GSTG);
#pragma unroll
            for (int t = 0; t < 4; t++)
                cp_async16(stg + ldst[t], lsrc[t] + (s + 2) * 32);
            cp_commit();
        }

        const uint32_t stg = sbase + (uint32_t)(cur * GSTG);
        cur++; if (cur == 3) cur = 0;

#pragma unroll
        for (int ks = 0; ks < 2; ks++) {
            const uint32_t cof = ks ? cof1 : cof0;
            uint32_t bf[4][2];
#pragma unroll
            for (int pair = 0; pair < 2; pair++) {
                uint32_t r0, r1, r2, r3;
                ldm_x4(r0, r1, r2, r3,
                       stg + GTIL + (uint32_t)((wn * 32 + pair * 16 + frow) * 64) + cof);
                bf[2 * pair][0] = r0; bf[2 * pair][1] = r2;
                bf[2 * pair + 1][0] = r1; bf[2 * pair + 1][1] = r3;
            }
#pragma unroll
            for (int mf = 0; mf < 4; mf++) {
                uint32_t af[4];
                ldm_x4(af[0], af[1], af[2], af[3],
                       stg + (uint32_t)((wm * 64 + mf * 16 + frow) * 64) + cof);
#pragma unroll
                for (int nf = 0; nf < 4; nf++)
                    mma_f16(acc[mf][nf], af, bf[nf]);
            }
        }
    }

    if (!QKV) {
#pragma unroll
        for (int mf = 0; mf < 4; mf++) {
#pragma unroll
            for (int nf = 0; nf < 4; nf++) {
                const int row0 = bm + wm * 64 + mf * 16 + (lane >> 2);
                const int col  = bn + wn * 32 + nf * 8 + (lane & 3) * 2;
                float2 bv = *(const float2*)&bias[col];
                float2 o0, o1;
                o0.x = acc[mf][nf][0] + bv.x;
                o0.y = acc[mf][nf][1] + bv.y;
                o1.x = acc[mf][nf][2] + bv.x;
                o1.y = acc[mf][nf][3] + bv.y;
                *(float2*)&Copt[(size_t)row0 * 2048 + col] = o0;
                *(float2*)&Copt[(size_t)(row0 + 8) * 2048 + col] = o1;
            }
        }
    } else {
        __half* dst = (z == 0) ? g_Q16 : (z == 1) ? g_K16 : g_V16;
#pragma unroll
        for (int mf = 0; mf < 4; mf++) {
#pragma unroll
            for (int nf = 0; nf < 4; nf++) {
                const int row0 = bm + wm * 64 + mf * 16 + (lane >> 2);
                const int col  = bn + wn * 32 + nf * 8 + (lane & 3) * 2;
                float2 bv = *(const float2*)&bias[col];
                *(uint32_t*)&dst[(size_t)row0 * 2048 + col] =
                    packh(alpha * (acc[mf][nf][0] + bv.x),
                          alpha * (acc[mf][nf][1] + bv.y));
                *(uint32_t*)&dst[(size_t)(row0 + 8) * 2048 + col] =
                    packh(alpha * (acc[mf][nf][2] + bv.x),
                          alpha * (acc[mf][nf][3] + bv.y));
            }
        }
    }
}

// ---------------------------------------------------------------------------
// fp16 HMMA causal flash attention: Bq=64, Bk=64, 128 threads (4 warps).
// Q/K/V swizzled 48KB smem; exp2-based softmax (log2e folded into Q scale);
// rescale-skip when no new row max; heavy-first CTA order.
// ---------------------------------------------------------------------------
#define QOFF 0
#define KOFF 16384
#define VOFF 32768
#define ATT_SMEM 49152
#define SWA(base, row, ch) ((base) + (uint32_t)((row) * 256 + (((ch) ^ ((row) & 7)) << 4)))

__global__ __launch_bounds__(128, 3) void flash_attn_f16()
{
    extern __shared__ __align__(16) char smem[];
    const uint32_t sb = smem_u32(smem);
    const int tid  = threadIdx.x;
    const int wid  = tid >> 5;
    const int lane = tid & 31;
    const int qt = gridDim.x - 1 - blockIdx.x;   // heavy-first
    const int bb = blockIdx.y;
    const int n  = bb / H_;
    const int h  = bb % H_;
    const int q0 = qt * 64;
    const int wr = q0 + wid * 16;
    const int colbase = h * DH;
    const int lr = lane >> 2;
    const int lc = lane & 3;
    const int frow = lane & 15;
    const int fhal = lane >> 4;

    // Prologue: Q tile -> smem, own commit group.
#pragma unroll
    for (int i = 0; i < 8; i++) {
        int c = tid + i * 128;
        int row = c >> 4;
        int ch  = c & 15;
        cp_async16(SWA(sb + QOFF, row, ch),
                   g_Q16 + ((size_t)(q0 + row) * NB + n) * 2048 + colbase + ch * 8);
    }
    cp_commit();

    float oacc[16][4];
#pragma unroll
    for (int f = 0; f < 16; f++)
#pragma unroll
        for (int q = 0; q < 4; q++) oacc[f][q] = 0.0f;
    float m_run[2] = {-1e30f, -1e30f};
    float l_run[2] = {0.0f, 0.0f};

    for (int jt = 0; jt <= qt; jt++) {
        const int k0 = jt * 64;
        __syncthreads();   // prior tile's smem readers done

#pragma unroll
        for (int i = 0; i < 8; i++) {
            int c = tid + i * 128;
            int row = c >> 4;
            int ch  = c & 15;
            cp_async16(SWA(sb + KOFF, row, ch),
                       g_K16 + ((size_t)(k0 + row) * NB + n) * 2048 + colbase + ch * 8);
        }
        cp_commit();
#pragma unroll
        for (int i = 0; i < 8; i++) {
            int c = tid + i * 128;
            int row = c >> 4;
            int ch  = c & 15;
            cp_async16(SWA(sb + VOFF, row, ch),
                       g_V16 + ((size_t)(k0 + row) * NB + n) * 2048 + colbase + ch * 8);
        }
        cp_commit();

        cp_wait1();        // Q + K ready (V may still be in flight)
        __syncthreads();

        const bool active = (k0 <= wr + 15);
        uint32_t ph[4][4];

        if (active) {
            float sacc[8][4];
#pragma unroll
            for (int j = 0; j < 8; j++)
#pragma unroll
                for (int q = 0; q < 4; q++) sacc[j][q] = 0.0f;

#pragma unroll
            for (int t = 0; t < 8; t++) {
                uint32_t af[4];
                {
                    int row = wid * 16 + frow;
                    ldm_x4(af[0], af[1], af[2], af[3], SWA(sb + QOFF, row, 2 * t + fhal));
                }
                // interleaved: one kf pair -> 2 MMAs (short live range)
#pragma unroll
                for (int g = 0; g < 4; g++) {
                    int row = (lane & 7) + ((lane >> 4) << 3) + 16 * g;
                    int ch  = 2 * t + ((lane >> 3) & 1);
                    uint32_t r0, r1, r2, r3;
                    ldm_x4(r0, r1, r2, r3, SWA(sb + KOFF, row, ch));
                    uint32_t k0f[2] = {r0, r1}, k1f[2] = {r2, r3};
                    mma_f16(sacc[2 * g],     af, k0f);
                    mma_f16(sacc[2 * g + 1], af, k1f);
                }
            }

            if (k0 + 63 > wr) {
                const int r0a = wr + lr, r1a = r0a + 8;
#pragma unroll
                for (int j = 0; j < 8; j++) {
                    int kc = k0 + 8 * j + 2 * lc;
                    if (kc > r0a)     sacc[j][0] = -1e30f;
                    if (kc + 1 > r0a) sacc[j][1] = -1e30f;
                    if (kc > r1a)     sacc[j][2] = -1e30f;
                    if (kc + 1 > r1a) sacc[j][3] = -1e30f;
                }
            }

            // Online softmax in base-2 (logits pre-scaled by log2e at Q-proj)
#pragma unroll
            for (int r = 0; r < 2; r++) {
                float mt = -1e30f;
#pragma unroll
                for (int j = 0; j < 8; j++)
                    mt = fmaxf(mt, fmaxf(sacc[j][2 * r], sacc[j][2 * r + 1]));
                mt = fmaxf(mt, __shfl_xor_sync(0xffffffffu, mt, 1));
                mt = fmaxf(mt, __shfl_xor_sync(0xffffffffu, mt, 2));
                const float mold = m_run[r];
                const float mnew = fmaxf(mold, mt);
                m_run[r] = mnew;
                float rs = 0.0f;
#pragma unroll
                for (int j = 0; j < 8; j++) {
                    sacc[j][2 * r]     = exp2f(sacc[j][2 * r] - mnew);
                    sacc[j][2 * r + 1] = exp2f(sacc[j][2 * r + 1] - mnew);
                    rs += sacc[j][2 * r] + sacc[j][2 * r + 1];
                }
                rs += __shfl_xor_sync(0xffffffffu, rs, 1);
                rs += __shfl_xor_sync(0xffffffffu, rs, 2);
                if (mnew > mold) {
                    const float corr = exp2f(mold - mnew);
                    l_run[r] = l_run[r] * corr + rs;
#pragma unroll
                    for (int f = 0; f < 16; f++) {
                        oacc[f][2 * r]     *= corr;
                        oacc[f][2 * r + 1] *= corr;
                    }
                } else {
                    l_run[r] += rs;
                }
            }

#pragma unroll
            for (int t2 = 0; t2 < 4; t2++) {
                const float* s0 = sacc[2 * t2];
                const float* s1 = sacc[2 * t2 + 1];
                ph[t2][0] = packh(s0[0], s0[1]);
                ph[t2][1] = packh(s0[2], s0[3]);
                ph[t2][2] = packh(s1[0], s1[1]);
                ph[t2][3] = packh(s1[2], s1[3]);
            }
        }

        cp_wait0();        // V ready
        __syncthreads();

        if (active) {
#pragma unroll
            for (int t2 = 0; t2 < 4; t2++) {
                int row = (lane & 7) + (((lane >> 3) & 1) << 3) + 16 * t2;
#pragma unroll
                for (int g = 0; g < 8; g++) {
                    int ch = 2 * g + (lane >> 4);
                    uint32_t r0, r1, r2, r3;
                    ldm_x4_t(r0, r1, r2, r3, SWA(sb + VOFF, row, ch));
                    uint32_t v0[2] = {r0, r1}, v1[2] = {r2, r3};
                    mma_f16(oacc[2 * g],     ph[t2], v0);
                    mma_f16(oacc[2 * g + 1], ph[t2], v1);
                }
            }
        }
    }

    // Epilogue: normalize, cast fp16, store into out-proj A buffer
    const float inv0 = 1.0f / l_run[0];
    const float inv1 = 1.0f / l_run[1];
    const size_t base0 = ((size_t)(wr + lr) * NB + n) * 2048 + colbase;
    const size_t base1 = ((size_t)(wr + lr + 8) * NB + n) * 2048 + colbase;
#pragma unroll
    for (int f = 0; f < 16; f++) {
        const int c = 8 * f + 2 * lc;
        *(uint32_t*)&g_A16[base0 + c] = packh(oacc[f][0] * inv0, oacc[f][1] * inv0);
        *(uint32_t*)&g_A16[base1 + c] = packh(oacc[f][2] * inv1, oacc[f][3] * inv1);
    }
}

// ---------------------------------------------------------------------------
extern "C" void kernel_launch(void* const* d_in, const int* in_sizes, int n_in,
                              void* d_out, int out_size)
{
    (void)in_sizes; (void)n_in; (void)out_size;
    const float* query = (const float*)d_in[0];
    const float* qw    = (const float*)d_in[1];
    const float* qb    = (const float*)d_in[2];
    const float* kw    = (const float*)d_in[3];
    const float* kb    = (const float*)d_in[4];
    const float* vw    = (const float*)d_in[5];
    const float* vb    = (const float*)d_in[6];
    const float* ow    = (const float*)d_in[7];
    const float* ob    = (const float*)d_in[8];
    float* out = (float*)d_out;

    // 1/sqrt(128) * log2(e): softmax runs in base 2.
    const float scale_l2e = (float)(0.08838834764831845 * 1.4426950408889634);

    const int totalThreads = (ROWS * I_ + 4 * WELEM) / 4;   // 6291456
    cast_all<<<totalThreads / 256, 256>>>(query, qw, kw, vw, ow);

    gemm_f16<true><<<dim3(16, 32, 3), 256, 3 * GSTG>>>(qb, kb, vb, nullptr, scale_l2e);

    flash_attn_f16<<<dim3(L_ / 64, NB * H_), 128, ATT_SMEM>>>();

    gemm_f16<false><<<dim3(16, 32, 1), 256, 3 * GSTG>>>(ob, nullptr, nullptr, out, 1.0f);
}